// round 1
// baseline (speedup 1.0000x reference)
#include <cuda_runtime.h>
#include <cstdint>
#include <cstddef>

#define NPTS   65536
#define CHN    512
#define C3     1536
#define PSZ    256
#define NHEAD  8
#define DHEAD  64
#define NBATCH 4
#define NCHUNK (NPTS / PSZ)   // 256

// ---------------- scratch (device globals: allocation-free) ----------------
__device__ float g_qkv[(size_t)NPTS * C3];       // serialized-order qkv  (384 MB)
__device__ float g_outp[(size_t)NPTS * CHN];     // attention out, original order (128 MB)
__device__ float g_cls_out[NCHUNK * CHN];        // per-chunk cls attention output
__device__ float g_cls_qkv[NBATCH * C3];         // cls token qkv per batch

// ---------------- K1: cls_qkv = cls_tokens @ Wqkv + bqkv ----------------
__global__ void cls_qkv_kernel(const float* __restrict__ cls_tokens,
                               const float* __restrict__ Wqkv,
                               const float* __restrict__ bqkv,
                               float* __restrict__ cls_qkv) {
    int idx = blockIdx.x * blockDim.x + threadIdx.x;
    if (idx >= NBATCH * C3) return;
    int b = idx / C3, o = idx % C3;
    float s = bqkv[o];
    #pragma unroll 4
    for (int k = 0; k < CHN; k++)
        s += cls_tokens[b * CHN + k] * Wqkv[(size_t)k * C3 + o];
    cls_qkv[idx] = s;
}

// ---------------- SGEMM: 128x128 tile, BK=8, 256 thr, 8x8 microtile --------
// MODE 0: C_out row = rowmap[m]  (scatter; used for qkv with rowmap=inverse)
// MODE 1: C_out row = m          (direct; used for proj)
template <int MODE>
__global__ __launch_bounds__(256)
void sgemm_kernel(const float* __restrict__ A, const float* __restrict__ B,
                  const float* __restrict__ bias, float* __restrict__ Cout,
                  const int* __restrict__ rowmap,
                  int Kdim, int lda, int ldb, int ldc) {
    __shared__ float As[2][8][128];
    __shared__ float Bs[2][8][128];

    const int tid   = threadIdx.x;
    const int tx    = tid & 15;
    const int ty    = tid >> 4;
    const int a_row = tid >> 1;
    const int a_col = (tid & 1) * 4;
    const int b_row = tid >> 5;
    const int b_col = (tid & 31) * 4;

    const float* Aptr = A + (size_t)(blockIdx.y * 128 + a_row) * lda + a_col;
    const float* Bptr = B + (size_t)b_row * ldb + blockIdx.x * 128 + b_col;

    float4 av = *(const float4*)Aptr;
    float4 bv = *(const float4*)Bptr;
    As[0][a_col + 0][a_row] = av.x;
    As[0][a_col + 1][a_row] = av.y;
    As[0][a_col + 2][a_row] = av.z;
    As[0][a_col + 3][a_row] = av.w;
    *(float4*)&Bs[0][b_row][b_col] = bv;
    __syncthreads();

    float acc[8][8];
    #pragma unroll
    for (int i = 0; i < 8; i++)
        #pragma unroll
        for (int j = 0; j < 8; j++) acc[i][j] = 0.f;

    const int nk = Kdim >> 3;
    for (int kt = 0; kt < nk; kt++) {
        const int cur = kt & 1;
        if (kt + 1 < nk) {
            av = *(const float4*)(Aptr + (kt + 1) * 8);
            bv = *(const float4*)(Bptr + (size_t)(kt + 1) * 8 * ldb);
        }
        #pragma unroll
        for (int k = 0; k < 8; k++) {
            float a_frag[8], b_frag[8];
            *(float4*)&a_frag[0] = *(const float4*)&As[cur][k][ty * 8];
            *(float4*)&a_frag[4] = *(const float4*)&As[cur][k][ty * 8 + 4];
            *(float4*)&b_frag[0] = *(const float4*)&Bs[cur][k][tx * 8];
            *(float4*)&b_frag[4] = *(const float4*)&Bs[cur][k][tx * 8 + 4];
            #pragma unroll
            for (int i = 0; i < 8; i++)
                #pragma unroll
                for (int j = 0; j < 8; j++)
                    acc[i][j] += a_frag[i] * b_frag[j];
        }
        if (kt + 1 < nk) {
            const int nxt = cur ^ 1;
            As[nxt][a_col + 0][a_row] = av.x;
            As[nxt][a_col + 1][a_row] = av.y;
            As[nxt][a_col + 2][a_row] = av.z;
            As[nxt][a_col + 3][a_row] = av.w;
            *(float4*)&Bs[nxt][b_row][b_col] = bv;
            __syncthreads();
        }
    }

    // epilogue: bias + (optional) row scatter
    const int col0 = blockIdx.x * 128 + tx * 8;
    float breg[8];
    #pragma unroll
    for (int j = 0; j < 8; j++) breg[j] = bias[col0 + j];

    #pragma unroll
    for (int i = 0; i < 8; i++) {
        int m    = blockIdx.y * 128 + ty * 8 + i;
        int orow = (MODE == 0) ? rowmap[m] : m;
        float4 v0, v1;
        v0.x = acc[i][0] + breg[0];  v0.y = acc[i][1] + breg[1];
        v0.z = acc[i][2] + breg[2];  v0.w = acc[i][3] + breg[3];
        v1.x = acc[i][4] + breg[4];  v1.y = acc[i][5] + breg[5];
        v1.z = acc[i][6] + breg[6];  v1.w = acc[i][7] + breg[7];
        float* dst = Cout + (size_t)orow * ldc + col0;
        *(float4*)dst       = v0;
        *(float4*)(dst + 4) = v1;
    }
}

// ---------------- K3: per-(chunk,head) attention, online softmax -----------
// Block = 288 threads. smem: K tile + V tile, 257 x 64 fp32 each (131584 B).
#define ATTN_SMEM (2 * 257 * 16 * (int)sizeof(float4))

__global__ __launch_bounds__(288)
void attn_kernel(const float* __restrict__ qkv,       // [NPTS, C3] serialized
                 const float* __restrict__ cls_qkv,   // [NBATCH, C3]
                 const int* __restrict__ order,       // [NPTS]
                 const int* __restrict__ offset,      // [NBATCH]
                 float* __restrict__ outp,            // [NPTS, CHN] original order
                 float* __restrict__ cls_out) {       // [NCHUNK, CHN]
    extern __shared__ float4 smem4[];
    float4* Ks = smem4;
    float4* Vs = smem4 + 257 * 16;

    const int chunk = blockIdx.x >> 3;
    const int head  = blockIdx.x & 7;
    const int tid   = threadIdx.x;

    // batch id for this chunk: searchsorted(offset, chunk*PSZ, 'right')
    const int start = chunk * PSZ;
    const int bid = (start >= offset[0]) + (start >= offset[1]) +
                    (start >= offset[2]) + (start >= offset[3]);

    const int koff = (CHN + head * DHEAD) / 4;       // float4 offset of K slice
    const int voff = (2 * CHN + head * DHEAD) / 4;   // float4 offset of V slice
    const float4* clsrow = (const float4*)(cls_qkv + (size_t)bid * C3);

    // cooperative K/V load (row 0 = cls token, rows 1..256 = chunk points)
    for (int e = tid; e < 257 * 16; e += 288) {
        int row = e >> 4, d4 = e & 15;
        const float4* rp = (row == 0)
            ? clsrow
            : (const float4*)(qkv + (size_t)(chunk * PSZ + row - 1) * C3);
        Ks[e] = rp[koff + d4];
        Vs[e] = rp[voff + d4];
    }
    __syncthreads();

    if (tid < 257) {
        const float4* qp = (tid == 0)
            ? clsrow + head * 16
            : (const float4*)(qkv + (size_t)(chunk * PSZ + tid - 1) * C3) + head * 16;
        float4 q[16];
        #pragma unroll
        for (int i = 0; i < 16; i++) q[i] = qp[i];

        float m = -1e30f, l = 0.f;
        float4 acc[16];
        #pragma unroll
        for (int i = 0; i < 16; i++) acc[i] = make_float4(0.f, 0.f, 0.f, 0.f);

        const float scale = 0.125f;  // dh^-0.5, dh=64
        for (int j = 0; j < 257; j++) {
            const float4* kr = Ks + j * 16;
            float s = 0.f;
            #pragma unroll
            for (int i = 0; i < 16; i++) {
                float4 kv = kr[i];
                s += q[i].x * kv.x + q[i].y * kv.y + q[i].z * kv.z + q[i].w * kv.w;
            }
            s *= scale;
            if (s > m) {
                float f = __expf(m - s);
                m = s;
                l *= f;
                #pragma unroll
                for (int i = 0; i < 16; i++) {
                    acc[i].x *= f; acc[i].y *= f; acc[i].z *= f; acc[i].w *= f;
                }
            }
            float p = __expf(s - m);
            l += p;
            const float4* vr = Vs + j * 16;
            #pragma unroll
            for (int i = 0; i < 16; i++) {
                float4 vv = vr[i];
                acc[i].x += p * vv.x; acc[i].y += p * vv.y;
                acc[i].z += p * vv.z; acc[i].w += p * vv.w;
            }
        }

        const float inv = 1.f / l;
        float4* dst;
        if (tid == 0) {
            dst = (float4*)(cls_out + (size_t)chunk * CHN) + head * 16;
        } else {
            int j_glob = chunk * PSZ + tid - 1;
            int drow   = order[j_glob];          // scatter so proj-GEMM A is coalesced
            dst = (float4*)(outp + (size_t)drow * CHN) + head * 16;
        }
        #pragma unroll
        for (int i = 0; i < 16; i++) {
            float4 o = acc[i];
            o.x *= inv; o.y *= inv; o.z *= inv; o.w *= inv;
            dst[i] = o;
        }
    }
}

// ---------------- K5: cls_feat = agg @ cls_out (per-batch mean) ------------
__global__ void cls_feat_kernel(const float* __restrict__ cls_out,
                                const int* __restrict__ offset,
                                float* __restrict__ out) {
    int b = blockIdx.x;
    int c = threadIdx.x;
    int o0 = offset[0], o1 = offset[1], o2 = offset[2], o3 = offset[3];
    float s = 0.f, cnt = 0.f;
    for (int ch = 0; ch < NCHUNK; ch++) {
        int start = ch * PSZ;
        int bid = (start >= o0) + (start >= o1) + (start >= o2) + (start >= o3);
        if (bid == b) { s += cls_out[(size_t)ch * CHN + c]; cnt += 1.f; }
    }
    out[(size_t)b * CHN + c] = s / cnt;
}

// ---------------- launch ----------------
extern "C" void kernel_launch(void* const* d_in, const int* in_sizes, int n_in,
                              void* d_out, int out_size) {
    const float* feat       = (const float*)d_in[0];
    const float* cls_tokens = (const float*)d_in[1];
    const float* Wqkv       = (const float*)d_in[2];
    const float* bqkv       = (const float*)d_in[3];
    const float* Wproj      = (const float*)d_in[4];
    const float* bproj      = (const float*)d_in[5];
    const int*   order      = (const int*)d_in[6];
    const int*   inverse    = (const int*)d_in[7];
    const int*   offset     = (const int*)d_in[8];
    float* out = (float*)d_out;

    float *qkv_p, *outp_p, *clsout_p, *clsqkv_p;
    cudaGetSymbolAddress((void**)&qkv_p, g_qkv);
    cudaGetSymbolAddress((void**)&outp_p, g_outp);
    cudaGetSymbolAddress((void**)&clsout_p, g_cls_out);
    cudaGetSymbolAddress((void**)&clsqkv_p, g_cls_qkv);

    // K1: cls qkv (tiny)
    cls_qkv_kernel<<<(NBATCH * C3 + 255) / 256, 256>>>(cls_tokens, Wqkv, bqkv, clsqkv_p);

    // K2: qkv = feat @ Wqkv + bqkv, rows scattered by inverse -> serialized order
    sgemm_kernel<0><<<dim3(C3 / 128, NPTS / 128), 256>>>(
        feat, Wqkv, bqkv, qkv_p, inverse, CHN, CHN, C3, C3);

    // K3: per-chunk-head attention
    cudaFuncSetAttribute(attn_kernel, cudaFuncAttributeMaxDynamicSharedMemorySize, ATTN_SMEM);
    attn_kernel<<<NCHUNK * NHEAD, 288, ATTN_SMEM>>>(
        qkv_p, clsqkv_p, order, offset, outp_p, clsout_p);

    // K4: feat_out = outp @ Wproj + bproj  (outp already in original order)
    sgemm_kernel<1><<<dim3(CHN / 128, NPTS / 128), 256>>>(
        outp_p, Wproj, bproj, out, nullptr, CHN, CHN, CHN, CHN);

    // K5: cls_feat
    cls_feat_kernel<<<NBATCH, CHN>>>(clsout_p, offset, out + (size_t)NPTS * CHN);
}

// round 2
// speedup vs baseline: 2.4699x; 2.4699x over previous
#include <cuda_runtime.h>
#include <cstdint>
#include <cstddef>

#define NPTS   65536
#define CHN    512
#define C3     1536
#define PSZ    256
#define NHEAD  8
#define DHEAD  64
#define NBATCH 4
#define NCHUNK (NPTS / PSZ)   // 256

// ---------------- scratch (device globals: allocation-free) ----------------
__device__ float g_qkv[(size_t)NPTS * C3];       // serialized-order qkv
__device__ float g_outp[(size_t)NPTS * CHN];     // attention out, original order
__device__ float g_cls_out[NCHUNK * CHN];        // per-chunk cls attention output
__device__ float g_cls_qkv[NBATCH * C3];         // cls token qkv per batch

__device__ __forceinline__ uint32_t f2tf32(float f) {
    uint32_t u;
    asm("cvt.rna.tf32.f32 %0, %1;" : "=r"(u) : "f"(f));
    return u;
}

// ---------------- K1: cls_qkv = cls_tokens @ Wqkv + bqkv ----------------
__global__ void cls_qkv_kernel(const float* __restrict__ cls_tokens,
                               const float* __restrict__ Wqkv,
                               const float* __restrict__ bqkv,
                               float* __restrict__ cls_qkv) {
    int idx = blockIdx.x * blockDim.x + threadIdx.x;
    if (idx >= NBATCH * C3) return;
    int b = idx / C3, o = idx % C3;
    float s = bqkv[o];
    #pragma unroll 4
    for (int k = 0; k < CHN; k++)
        s += cls_tokens[b * CHN + k] * Wqkv[(size_t)k * C3 + o];
    cls_qkv[idx] = s;
}

// ---------------- tf32 tensor-core GEMM: 128x128x32, 256 thr ----------------
// MODE 0: C row = rowmap[m] (scatter), MODE 1: C row = m.
// Dynamic smem: As[2][128][36] + Bs[2][32][136] uint32 (tf32 bits) = 71680 B.
#define AS_STRIDE 36
#define BS_STRIDE 136
#define AS_BUF (128 * AS_STRIDE)          // 4608 words
#define BS_BUF (32 * BS_STRIDE)           // 4352 words
#define GEMM_SMEM ((2 * AS_BUF + 2 * BS_BUF) * 4)   // 71680 bytes

template <int MODE>
__global__ __launch_bounds__(256)
void tgemm_kernel(const float* __restrict__ A, const float* __restrict__ B,
                  const float* __restrict__ bias, float* __restrict__ Cout,
                  const int* __restrict__ rowmap,
                  int Kdim, int lda, int ldb, int ldc) {
    extern __shared__ uint32_t sm[];
    uint32_t* As = sm;                 // [2][128][AS_STRIDE]  (m-major)
    uint32_t* Bs = sm + 2 * AS_BUF;    // [2][32][BS_STRIDE]   (k-major)

    const int tid  = threadIdx.x;
    const int lane = tid & 31;
    const int warp = tid >> 5;
    const int wm   = warp >> 2;        // 0..1
    const int wn   = warp & 3;         // 0..3
    const int g    = lane >> 2;        // 0..7
    const int t    = lane & 3;         // 0..3

    // global-load assignments
    const int a_row = tid >> 1;                 // 0..127
    const int a_k0  = (tid & 1) * 16;           // 0 or 16
    const float* Aptr = A + (size_t)(blockIdx.y * 128 + a_row) * lda + a_k0;
    const float* Bbase = B + blockIdx.x * 128;

    float4 areg[4], breg4[4];
    // prefetch tile 0
    #pragma unroll
    for (int i = 0; i < 4; i++)
        areg[i] = *(const float4*)(Aptr + i * 4);
    #pragma unroll
    for (int i = 0; i < 4; i++) {
        int idx = tid + 256 * i;
        int r = idx >> 5, c4 = idx & 31;
        breg4[i] = *(const float4*)(Bbase + (size_t)r * ldb + c4 * 4);
    }
    // store tile 0
    {
        uint32_t* as = As + a_row * AS_STRIDE + a_k0;
        #pragma unroll
        for (int i = 0; i < 4; i++) {
            const float* fp = (const float*)&areg[i];
            as[i * 4 + 0] = f2tf32(fp[0]); as[i * 4 + 1] = f2tf32(fp[1]);
            as[i * 4 + 2] = f2tf32(fp[2]); as[i * 4 + 3] = f2tf32(fp[3]);
        }
        #pragma unroll
        for (int i = 0; i < 4; i++) {
            int idx = tid + 256 * i;
            int r = idx >> 5, c4 = idx & 31;
            const float* fp = (const float*)&breg4[i];
            uint32_t* bs = Bs + r * BS_STRIDE + c4 * 4;
            bs[0] = f2tf32(fp[0]); bs[1] = f2tf32(fp[1]);
            bs[2] = f2tf32(fp[2]); bs[3] = f2tf32(fp[3]);
        }
    }
    __syncthreads();

    float c[4][4][4];
    #pragma unroll
    for (int mi = 0; mi < 4; mi++)
        #pragma unroll
        for (int ni = 0; ni < 4; ni++)
            #pragma unroll
            for (int r = 0; r < 4; r++) c[mi][ni][r] = 0.f;

    const int nk = Kdim >> 5;
    for (int kt = 0; kt < nk; kt++) {
        const int cur = kt & 1;
        if (kt + 1 < nk) {
            #pragma unroll
            for (int i = 0; i < 4; i++)
                areg[i] = *(const float4*)(Aptr + (kt + 1) * 32 + i * 4);
            #pragma unroll
            for (int i = 0; i < 4; i++) {
                int idx = tid + 256 * i;
                int r = idx >> 5, c4 = idx & 31;
                breg4[i] = *(const float4*)(Bbase + (size_t)((kt + 1) * 32 + r) * ldb + c4 * 4);
            }
        }

        const uint32_t* asb = As + cur * AS_BUF;
        const uint32_t* bsb = Bs + cur * BS_BUF;
        #pragma unroll
        for (int ks = 0; ks < 4; ks++) {
            const int k0 = ks * 8;
            uint32_t af[4][4], bf[4][2];
            #pragma unroll
            for (int mi = 0; mi < 4; mi++) {
                const int row = wm * 64 + mi * 16 + g;
                af[mi][0] = asb[(row)     * AS_STRIDE + k0 + t];
                af[mi][1] = asb[(row + 8) * AS_STRIDE + k0 + t];
                af[mi][2] = asb[(row)     * AS_STRIDE + k0 + t + 4];
                af[mi][3] = asb[(row + 8) * AS_STRIDE + k0 + t + 4];
            }
            #pragma unroll
            for (int ni = 0; ni < 4; ni++) {
                const int col = wn * 32 + ni * 8 + g;
                bf[ni][0] = bsb[(k0 + t)     * BS_STRIDE + col];
                bf[ni][1] = bsb[(k0 + t + 4) * BS_STRIDE + col];
            }
            #pragma unroll
            for (int mi = 0; mi < 4; mi++)
                #pragma unroll
                for (int ni = 0; ni < 4; ni++) {
                    asm volatile(
                        "mma.sync.aligned.m16n8k8.row.col.f32.tf32.tf32.f32 "
                        "{%0,%1,%2,%3}, {%4,%5,%6,%7}, {%8,%9}, {%0,%1,%2,%3};"
                        : "+f"(c[mi][ni][0]), "+f"(c[mi][ni][1]),
                          "+f"(c[mi][ni][2]), "+f"(c[mi][ni][3])
                        : "r"(af[mi][0]), "r"(af[mi][1]), "r"(af[mi][2]), "r"(af[mi][3]),
                          "r"(bf[ni][0]), "r"(bf[ni][1]));
                }
        }

        if (kt + 1 < nk) {
            const int nxt = cur ^ 1;
            uint32_t* as = As + nxt * AS_BUF + a_row * AS_STRIDE + a_k0;
            #pragma unroll
            for (int i = 0; i < 4; i++) {
                const float* fp = (const float*)&areg[i];
                as[i * 4 + 0] = f2tf32(fp[0]); as[i * 4 + 1] = f2tf32(fp[1]);
                as[i * 4 + 2] = f2tf32(fp[2]); as[i * 4 + 3] = f2tf32(fp[3]);
            }
            #pragma unroll
            for (int i = 0; i < 4; i++) {
                int idx = tid + 256 * i;
                int r = idx >> 5, c4 = idx & 31;
                const float* fp = (const float*)&breg4[i];
                uint32_t* bs = Bs + nxt * BS_BUF + r * BS_STRIDE + c4 * 4;
                bs[0] = f2tf32(fp[0]); bs[1] = f2tf32(fp[1]);
                bs[2] = f2tf32(fp[2]); bs[3] = f2tf32(fp[3]);
            }
            __syncthreads();
        }
    }

    // epilogue: bias + optional row scatter (float2 stores; lanes 0-3 form a
    // contiguous 32B sector per row, so scatter costs no write amplification)
    float2 bv[4];
    #pragma unroll
    for (int ni = 0; ni < 4; ni++)
        bv[ni] = *(const float2*)&bias[blockIdx.x * 128 + wn * 32 + ni * 8 + t * 2];

    #pragma unroll
    for (int mi = 0; mi < 4; mi++) {
        const int m0 = blockIdx.y * 128 + wm * 64 + mi * 16 + g;
        const int r0 = (MODE == 0) ? rowmap[m0]     : m0;
        const int r1 = (MODE == 0) ? rowmap[m0 + 8] : m0 + 8;
        #pragma unroll
        for (int ni = 0; ni < 4; ni++) {
            const int col = blockIdx.x * 128 + wn * 32 + ni * 8 + t * 2;
            float2 v0 = make_float2(c[mi][ni][0] + bv[ni].x, c[mi][ni][1] + bv[ni].y);
            float2 v1 = make_float2(c[mi][ni][2] + bv[ni].x, c[mi][ni][3] + bv[ni].y);
            *(float2*)(Cout + (size_t)r0 * ldc + col) = v0;
            *(float2*)(Cout + (size_t)r1 * ldc + col) = v1;
        }
    }
}

// ---------------- K3: per-(chunk,head) attention, online softmax -----------
#define ATTN_SMEM (2 * 257 * 16 * (int)sizeof(float4))

__global__ __launch_bounds__(288)
void attn_kernel(const float* __restrict__ qkv,       // [NPTS, C3] serialized
                 const float* __restrict__ cls_qkv,   // [NBATCH, C3]
                 const int* __restrict__ order,       // [NPTS]
                 const int* __restrict__ offset,      // [NBATCH]
                 float* __restrict__ outp,            // [NPTS, CHN] original order
                 float* __restrict__ cls_out) {       // [NCHUNK, CHN]
    extern __shared__ float4 smem4[];
    float4* Ks = smem4;
    float4* Vs = smem4 + 257 * 16;

    const int chunk = blockIdx.x >> 3;
    const int head  = blockIdx.x & 7;
    const int tid   = threadIdx.x;

    const int start = chunk * PSZ;
    const int bid = (start >= offset[0]) + (start >= offset[1]) +
                    (start >= offset[2]) + (start >= offset[3]);

    const int koff = (CHN + head * DHEAD) / 4;
    const int voff = (2 * CHN + head * DHEAD) / 4;
    const float4* clsrow = (const float4*)(cls_qkv + (size_t)bid * C3);

    for (int e = tid; e < 257 * 16; e += 288) {
        int row = e >> 4, d4 = e & 15;
        const float4* rp = (row == 0)
            ? clsrow
            : (const float4*)(qkv + (size_t)(chunk * PSZ + row - 1) * C3);
        Ks[e] = rp[koff + d4];
        Vs[e] = rp[voff + d4];
    }
    __syncthreads();

    if (tid < 257) {
        const float4* qp = (tid == 0)
            ? clsrow + head * 16
            : (const float4*)(qkv + (size_t)(chunk * PSZ + tid - 1) * C3) + head * 16;
        float4 q[16];
        #pragma unroll
        for (int i = 0; i < 16; i++) q[i] = qp[i];

        float m = -1e30f, l = 0.f;
        float4 acc[16];
        #pragma unroll
        for (int i = 0; i < 16; i++) acc[i] = make_float4(0.f, 0.f, 0.f, 0.f);

        const float scale = 0.125f;
        for (int j = 0; j < 257; j++) {
            const float4* kr = Ks + j * 16;
            float s = 0.f;
            #pragma unroll
            for (int i = 0; i < 16; i++) {
                float4 kv = kr[i];
                s += q[i].x * kv.x + q[i].y * kv.y + q[i].z * kv.z + q[i].w * kv.w;
            }
            s *= scale;
            if (s > m) {
                float f = __expf(m - s);
                m = s;
                l *= f;
                #pragma unroll
                for (int i = 0; i < 16; i++) {
                    acc[i].x *= f; acc[i].y *= f; acc[i].z *= f; acc[i].w *= f;
                }
            }
            float p = __expf(s - m);
            l += p;
            const float4* vr = Vs + j * 16;
            #pragma unroll
            for (int i = 0; i < 16; i++) {
                float4 vv = vr[i];
                acc[i].x += p * vv.x; acc[i].y += p * vv.y;
                acc[i].z += p * vv.z; acc[i].w += p * vv.w;
            }
        }

        const float inv = 1.f / l;
        float4* dst;
        if (tid == 0) {
            dst = (float4*)(cls_out + (size_t)chunk * CHN) + head * 16;
        } else {
            int j_glob = chunk * PSZ + tid - 1;
            int drow   = order[j_glob];
            dst = (float4*)(outp + (size_t)drow * CHN) + head * 16;
        }
        #pragma unroll
        for (int i = 0; i < 16; i++) {
            float4 o = acc[i];
            o.x *= inv; o.y *= inv; o.z *= inv; o.w *= inv;
            dst[i] = o;
        }
    }
}

// ---------------- K5: cls_feat = per-batch mean of cls_out ------------
__global__ void cls_feat_kernel(const float* __restrict__ cls_out,
                                const int* __restrict__ offset,
                                float* __restrict__ out) {
    int b = blockIdx.x;
    int c = threadIdx.x;
    int o0 = offset[0], o1 = offset[1], o2 = offset[2], o3 = offset[3];
    float s = 0.f, cnt = 0.f;
    for (int ch = 0; ch < NCHUNK; ch++) {
        int start = ch * PSZ;
        int bid = (start >= o0) + (start >= o1) + (start >= o2) + (start >= o3);
        if (bid == b) { s += cls_out[(size_t)ch * CHN + c]; cnt += 1.f; }
    }
    out[(size_t)b * CHN + c] = s / cnt;
}

// ---------------- launch ----------------
extern "C" void kernel_launch(void* const* d_in, const int* in_sizes, int n_in,
                              void* d_out, int out_size) {
    const float* feat       = (const float*)d_in[0];
    const float* cls_tokens = (const float*)d_in[1];
    const float* Wqkv       = (const float*)d_in[2];
    const float* bqkv       = (const float*)d_in[3];
    const float* Wproj      = (const float*)d_in[4];
    const float* bproj      = (const float*)d_in[5];
    const int*   order      = (const int*)d_in[6];
    const int*   inverse    = (const int*)d_in[7];
    const int*   offset     = (const int*)d_in[8];
    float* out = (float*)d_out;

    float *qkv_p, *outp_p, *clsout_p, *clsqkv_p;
    cudaGetSymbolAddress((void**)&qkv_p, g_qkv);
    cudaGetSymbolAddress((void**)&outp_p, g_outp);
    cudaGetSymbolAddress((void**)&clsout_p, g_cls_out);
    cudaGetSymbolAddress((void**)&clsqkv_p, g_cls_qkv);

    cudaFuncSetAttribute(tgemm_kernel<0>, cudaFuncAttributeMaxDynamicSharedMemorySize, GEMM_SMEM);
    cudaFuncSetAttribute(tgemm_kernel<1>, cudaFuncAttributeMaxDynamicSharedMemorySize, GEMM_SMEM);
    cudaFuncSetAttribute(attn_kernel, cudaFuncAttributeMaxDynamicSharedMemorySize, ATTN_SMEM);

    // K1: cls qkv (tiny)
    cls_qkv_kernel<<<(NBATCH * C3 + 255) / 256, 256>>>(cls_tokens, Wqkv, bqkv, clsqkv_p);

    // K2: qkv = feat @ Wqkv + bqkv, rows scattered by inverse -> serialized order
    tgemm_kernel<0><<<dim3(C3 / 128, NPTS / 128), 256, GEMM_SMEM>>>(
        feat, Wqkv, bqkv, qkv_p, inverse, CHN, CHN, C3, C3);

    // K3: per-chunk-head attention
    attn_kernel<<<NCHUNK * NHEAD, 288, ATTN_SMEM>>>(
        qkv_p, clsqkv_p, order, offset, outp_p, clsout_p);

    // K4: feat_out = outp @ Wproj + bproj (outp already in original order)
    tgemm_kernel<1><<<dim3(CHN / 128, NPTS / 128), 256, GEMM_SMEM>>>(
        outp_p, Wproj, bproj, out, nullptr, CHN, CHN, CHN, CHN);

    // K5: cls_feat
    cls_feat_kernel<<<NBATCH, CHN>>>(clsout_p, offset, out + (size_t)NPTS * CHN);
}

// round 5
// speedup vs baseline: 3.3512x; 1.3568x over previous
#include <cuda_runtime.h>
#include <cstdint>
#include <cstddef>

#define NPTS   65536
#define CHN    512
#define C3     1536
#define PSZ    256
#define NHEAD  8
#define DHEAD  64
#define NBATCH 4
#define NCHUNK (NPTS / PSZ)   // 256

// ---------------- scratch (device globals: allocation-free) ----------------
__device__ float g_qkv[(size_t)NPTS * C3];       // serialized-order qkv
__device__ float g_outp[(size_t)NPTS * CHN];     // attention out, original order
__device__ float g_cls_out[NCHUNK * CHN];        // per-chunk cls attention output
__device__ float g_cls_qkv[NBATCH * C3];         // cls token qkv per batch

__device__ __forceinline__ uint32_t f2tf32(float f) {
    uint32_t u;
    asm("cvt.rna.tf32.f32 %0, %1;" : "=r"(u) : "f"(f));
    return u;
}

__device__ __forceinline__ void mma_tf32(float* c, const uint32_t* a,
                                         uint32_t b0, uint32_t b1) {
    asm volatile(
        "mma.sync.aligned.m16n8k8.row.col.f32.tf32.tf32.f32 "
        "{%0,%1,%2,%3}, {%4,%5,%6,%7}, {%8,%9}, {%0,%1,%2,%3};"
        : "+f"(c[0]), "+f"(c[1]), "+f"(c[2]), "+f"(c[3])
        : "r"(a[0]), "r"(a[1]), "r"(a[2]), "r"(a[3]), "r"(b0), "r"(b1));
}

// ---------------- K1: cls_qkv = cls_tokens @ Wqkv + bqkv ----------------
__global__ void cls_qkv_kernel(const float* __restrict__ cls_tokens,
                               const float* __restrict__ Wqkv,
                               const float* __restrict__ bqkv,
                               float* __restrict__ cls_qkv) {
    int idx = blockIdx.x * blockDim.x + threadIdx.x;
    if (idx >= NBATCH * C3) return;
    int b = idx / C3, o = idx % C3;
    float s = bqkv[o];
    #pragma unroll 4
    for (int k = 0; k < CHN; k++)
        s += cls_tokens[b * CHN + k] * Wqkv[(size_t)k * C3 + o];
    cls_qkv[idx] = s;
}

// ---------------- tf32 tensor-core GEMM: 128x128x32, 256 thr ----------------
#define AS_STRIDE 36
#define BS_STRIDE 136
#define AS_BUF (128 * AS_STRIDE)
#define BS_BUF (32 * BS_STRIDE)
#define GEMM_SMEM ((2 * AS_BUF + 2 * BS_BUF) * 4)   // 71680 bytes

template <int MODE>
__global__ __launch_bounds__(256)
void tgemm_kernel(const float* __restrict__ A, const float* __restrict__ B,
                  const float* __restrict__ bias, float* __restrict__ Cout,
                  const int* __restrict__ rowmap,
                  int Kdim, int lda, int ldb, int ldc) {
    extern __shared__ uint32_t sm[];
    uint32_t* As = sm;
    uint32_t* Bs = sm + 2 * AS_BUF;

    const int tid  = threadIdx.x;
    const int lane = tid & 31;
    const int warp = tid >> 5;
    const int wm   = warp >> 2;
    const int wn   = warp & 3;
    const int g    = lane >> 2;
    const int t    = lane & 3;

    const int a_row = tid >> 1;
    const int a_k0  = (tid & 1) * 16;
    const float* Aptr = A + (size_t)(blockIdx.y * 128 + a_row) * lda + a_k0;
    const float* Bbase = B + blockIdx.x * 128;

    float4 areg[4], breg4[4];
    #pragma unroll
    for (int i = 0; i < 4; i++)
        areg[i] = *(const float4*)(Aptr + i * 4);
    #pragma unroll
    for (int i = 0; i < 4; i++) {
        int idx = tid + 256 * i;
        int r = idx >> 5, c4 = idx & 31;
        breg4[i] = *(const float4*)(Bbase + (size_t)r * ldb + c4 * 4);
    }
    {
        uint32_t* as = As + a_row * AS_STRIDE + a_k0;
        #pragma unroll
        for (int i = 0; i < 4; i++) {
            const float* fp = (const float*)&areg[i];
            as[i * 4 + 0] = f2tf32(fp[0]); as[i * 4 + 1] = f2tf32(fp[1]);
            as[i * 4 + 2] = f2tf32(fp[2]); as[i * 4 + 3] = f2tf32(fp[3]);
        }
        #pragma unroll
        for (int i = 0; i < 4; i++) {
            int idx = tid + 256 * i;
            int r = idx >> 5, c4 = idx & 31;
            const float* fp = (const float*)&breg4[i];
            uint32_t* bs = Bs + r * BS_STRIDE + c4 * 4;
            bs[0] = f2tf32(fp[0]); bs[1] = f2tf32(fp[1]);
            bs[2] = f2tf32(fp[2]); bs[3] = f2tf32(fp[3]);
        }
    }
    __syncthreads();

    float c[4][4][4];
    #pragma unroll
    for (int mi = 0; mi < 4; mi++)
        #pragma unroll
        for (int ni = 0; ni < 4; ni++)
            #pragma unroll
            for (int r = 0; r < 4; r++) c[mi][ni][r] = 0.f;

    const int nk = Kdim >> 5;
    for (int kt = 0; kt < nk; kt++) {
        const int cur = kt & 1;
        if (kt + 1 < nk) {
            #pragma unroll
            for (int i = 0; i < 4; i++)
                areg[i] = *(const float4*)(Aptr + (kt + 1) * 32 + i * 4);
            #pragma unroll
            for (int i = 0; i < 4; i++) {
                int idx = tid + 256 * i;
                int r = idx >> 5, c4 = idx & 31;
                breg4[i] = *(const float4*)(Bbase + (size_t)((kt + 1) * 32 + r) * ldb + c4 * 4);
            }
        }

        const uint32_t* asb = As + cur * AS_BUF;
        const uint32_t* bsb = Bs + cur * BS_BUF;
        #pragma unroll
        for (int ks = 0; ks < 4; ks++) {
            const int k0 = ks * 8;
            uint32_t af[4][4], bf[4][2];
            #pragma unroll
            for (int mi = 0; mi < 4; mi++) {
                const int row = wm * 64 + mi * 16 + g;
                af[mi][0] = asb[(row)     * AS_STRIDE + k0 + t];
                af[mi][1] = asb[(row + 8) * AS_STRIDE + k0 + t];
                af[mi][2] = asb[(row)     * AS_STRIDE + k0 + t + 4];
                af[mi][3] = asb[(row + 8) * AS_STRIDE + k0 + t + 4];
            }
            #pragma unroll
            for (int ni = 0; ni < 4; ni++) {
                const int col = wn * 32 + ni * 8 + g;
                bf[ni][0] = bsb[(k0 + t)     * BS_STRIDE + col];
                bf[ni][1] = bsb[(k0 + t + 4) * BS_STRIDE + col];
            }
            #pragma unroll
            for (int mi = 0; mi < 4; mi++)
                #pragma unroll
                for (int ni = 0; ni < 4; ni++)
                    mma_tf32(c[mi][ni], af[mi], bf[ni][0], bf[ni][1]);
        }

        if (kt + 1 < nk) {
            const int nxt = cur ^ 1;
            uint32_t* as = As + nxt * AS_BUF + a_row * AS_STRIDE + a_k0;
            #pragma unroll
            for (int i = 0; i < 4; i++) {
                const float* fp = (const float*)&areg[i];
                as[i * 4 + 0] = f2tf32(fp[0]); as[i * 4 + 1] = f2tf32(fp[1]);
                as[i * 4 + 2] = f2tf32(fp[2]); as[i * 4 + 3] = f2tf32(fp[3]);
            }
            #pragma unroll
            for (int i = 0; i < 4; i++) {
                int idx = tid + 256 * i;
                int r = idx >> 5, c4 = idx & 31;
                const float* fp = (const float*)&breg4[i];
                uint32_t* bs = Bs + nxt * BS_BUF + r * BS_STRIDE + c4 * 4;
                bs[0] = f2tf32(fp[0]); bs[1] = f2tf32(fp[1]);
                bs[2] = f2tf32(fp[2]); bs[3] = f2tf32(fp[3]);
            }
            __syncthreads();
        }
    }

    float2 bv[4];
    #pragma unroll
    for (int ni = 0; ni < 4; ni++)
        bv[ni] = *(const float2*)&bias[blockIdx.x * 128 + wn * 32 + ni * 8 + t * 2];

    #pragma unroll
    for (int mi = 0; mi < 4; mi++) {
        const int m0 = blockIdx.y * 128 + wm * 64 + mi * 16 + g;
        const int r0 = (MODE == 0) ? rowmap[m0]     : m0;
        const int r1 = (MODE == 0) ? rowmap[m0 + 8] : m0 + 8;
        #pragma unroll
        for (int ni = 0; ni < 4; ni++) {
            const int col = blockIdx.x * 128 + wn * 32 + ni * 8 + t * 2;
            float2 v0 = make_float2(c[mi][ni][0] + bv[ni].x, c[mi][ni][1] + bv[ni].y);
            float2 v1 = make_float2(c[mi][ni][2] + bv[ni].x, c[mi][ni][3] + bv[ni].y);
            *(float2*)(Cout + (size_t)r0 * ldc + col) = v0;
            *(float2*)(Cout + (size_t)r1 * ldc + col) = v1;
        }
    }
}

// ---------------- K3: tensor-core flash attention (point queries) ----------
// Block = 256 thr, one block per (chunk, head, half-of-128-queries).
// Keys 0..255 = chunk points, key 256 = cls token, 257..263 = zero pad (masked).
#define KT_STRIDE 264
#define VS_STRIDE 72
#define QS_STRIDE 72
#define KT_WORDS (64 * KT_STRIDE)          // 16896
#define VS_WORDS (264 * VS_STRIDE)         // 19008
#define QS_WORDS (128 * QS_STRIDE)         // 9216
#define AT_SMEM ((KT_WORDS + VS_WORDS + QS_WORDS) * 4)   // 180480 bytes

__global__ __launch_bounds__(256)
void attn_tc_kernel(const float* __restrict__ qkv,       // [NPTS, C3] serialized
                    const float* __restrict__ cls_qkv,   // [NBATCH, C3]
                    const int* __restrict__ order,       // [NPTS]
                    const int* __restrict__ offset,      // [NBATCH]
                    float* __restrict__ outp) {          // [NPTS, CHN] orig order
    extern __shared__ uint32_t sm[];
    uint32_t* Kt = sm;                      // [64][264]   (d-major, keys)
    uint32_t* Vs = sm + KT_WORDS;           // [264][72]   (key-major, dh)
    uint32_t* Qs = sm + KT_WORDS + VS_WORDS; // [128][72]  Q, later P staging

    const int bx    = blockIdx.x;
    const int chunk = bx >> 4;
    const int head  = (bx >> 1) & 7;
    const int half  = bx & 1;
    const int tid   = threadIdx.x;

    const int start = chunk * PSZ;
    const int bid = (start >= offset[0]) + (start >= offset[1]) +
                    (start >= offset[2]) + (start >= offset[3]);
    const float* clsrow = cls_qkv + (size_t)bid * C3;

    // zero pad: Kt cols 257..263, Vs rows 257..263
    for (int e = tid; e < 64 * 7; e += 256) {
        int d = e / 7, k = e % 7;
        Kt[d * KT_STRIDE + 257 + k] = 0;
    }
    for (int e = tid; e < 7 * VS_STRIDE; e += 256)
        Vs[257 * VS_STRIDE + e] = 0;

    // K: one key row per thread, transposed store (conflict-free)
    for (int key = tid; key < 257; key += 256) {
        const float* base = (key < 256)
            ? qkv + (size_t)(chunk * PSZ + key) * C3 : clsrow;
        #pragma unroll
        for (int d4 = 0; d4 < 16; d4++) {
            float4 kv = *(const float4*)(base + CHN + head * DHEAD + d4 * 4);
            Kt[(d4 * 4 + 0) * KT_STRIDE + key] = f2tf32(kv.x);
            Kt[(d4 * 4 + 1) * KT_STRIDE + key] = f2tf32(kv.y);
            Kt[(d4 * 4 + 2) * KT_STRIDE + key] = f2tf32(kv.z);
            Kt[(d4 * 4 + 3) * KT_STRIDE + key] = f2tf32(kv.w);
        }
    }
    // V: float4-coalesced
    for (int e = tid; e < 257 * 16; e += 256) {
        int key = e >> 4, d4 = e & 15;
        const float* base = (key < 256)
            ? qkv + (size_t)(chunk * PSZ + key) * C3 : clsrow;
        float4 vv = *(const float4*)(base + 2 * CHN + head * DHEAD + d4 * 4);
        uint32_t* dst = Vs + key * VS_STRIDE + d4 * 4;
        dst[0] = f2tf32(vv.x); dst[1] = f2tf32(vv.y);
        dst[2] = f2tf32(vv.z); dst[3] = f2tf32(vv.w);
    }
    // Q (scale folded): float4-coalesced
    for (int e = tid; e < 128 * 16; e += 256) {
        int i = e >> 4, d4 = e & 15;
        const float* base = qkv + (size_t)(chunk * PSZ + half * 128 + i) * C3;
        float4 qv = *(const float4*)(base + head * DHEAD + d4 * 4);
        uint32_t* dst = Qs + i * QS_STRIDE + d4 * 4;
        dst[0] = f2tf32(qv.x * 0.125f); dst[1] = f2tf32(qv.y * 0.125f);
        dst[2] = f2tf32(qv.z * 0.125f); dst[3] = f2tf32(qv.w * 0.125f);
    }
    __syncthreads();

    const int warp = tid >> 5, lane = tid & 31;
    const int g = lane >> 2, t = lane & 3;
    const int mrow = warp * 16;

    // Q fragments (resident), then Qs region becomes per-warp P staging
    uint32_t qf[8][4];
    #pragma unroll
    for (int ks = 0; ks < 8; ks++) {
        qf[ks][0] = Qs[(mrow + g)     * QS_STRIDE + ks * 8 + t];
        qf[ks][1] = Qs[(mrow + g + 8) * QS_STRIDE + ks * 8 + t];
        qf[ks][2] = Qs[(mrow + g)     * QS_STRIDE + ks * 8 + t + 4];
        qf[ks][3] = Qs[(mrow + g + 8) * QS_STRIDE + ks * 8 + t + 4];
    }
    __syncwarp();

    float o[8][4];
    #pragma unroll
    for (int nt = 0; nt < 8; nt++)
        #pragma unroll
        for (int r = 0; r < 4; r++) o[nt][r] = 0.f;
    float m0 = -1e30f, m1 = -1e30f, l0 = 0.f, l1 = 0.f;

    for (int kb = 0; kb < 5; kb++) {
        const int nnt = (kb < 4) ? 8 : 1;   // last block: 8 keys (cls + 7 pad)
        float s[8][4];
        #pragma unroll
        for (int nt = 0; nt < 8; nt++)
            #pragma unroll
            for (int r = 0; r < 4; r++) s[nt][r] = 0.f;

        // S = Q @ K^T
        #pragma unroll
        for (int ks = 0; ks < 8; ks++) {
            #pragma unroll
            for (int nt = 0; nt < 8; nt++) {
                if (nt >= nnt) break;
                uint32_t b0 = Kt[(ks * 8 + t)     * KT_STRIDE + kb * 64 + nt * 8 + g];
                uint32_t b1 = Kt[(ks * 8 + t + 4) * KT_STRIDE + kb * 64 + nt * 8 + g];
                mma_tf32(s[nt], qf[ks], b0, b1);
            }
        }
        if (kb == 4) {   // mask cols > 256 (only col 256 = cls key valid)
            if (t != 0) { s[0][0] = -1e30f; s[0][2] = -1e30f; }
            s[0][1] = -1e30f; s[0][3] = -1e30f;
        }

        // online softmax
        float mx0 = -1e30f, mx1 = -1e30f;
        #pragma unroll
        for (int nt = 0; nt < 8; nt++) {
            if (nt >= nnt) break;
            mx0 = fmaxf(mx0, fmaxf(s[nt][0], s[nt][1]));
            mx1 = fmaxf(mx1, fmaxf(s[nt][2], s[nt][3]));
        }
        mx0 = fmaxf(mx0, __shfl_xor_sync(0xffffffffu, mx0, 1));
        mx0 = fmaxf(mx0, __shfl_xor_sync(0xffffffffu, mx0, 2));
        mx1 = fmaxf(mx1, __shfl_xor_sync(0xffffffffu, mx1, 1));
        mx1 = fmaxf(mx1, __shfl_xor_sync(0xffffffffu, mx1, 2));
        float nm0 = fmaxf(m0, mx0), nm1 = fmaxf(m1, mx1);
        float f0 = __expf(m0 - nm0), f1 = __expf(m1 - nm1);
        m0 = nm0; m1 = nm1; l0 *= f0; l1 *= f1;
        #pragma unroll
        for (int nt = 0; nt < 8; nt++) {
            o[nt][0] *= f0; o[nt][1] *= f0;
            o[nt][2] *= f1; o[nt][3] *= f1;
        }
        // P -> smem (warp-private rows of Qs)
        #pragma unroll
        for (int nt = 0; nt < 8; nt++) {
            if (nt >= nnt) break;
            float p0 = __expf(s[nt][0] - m0), p1 = __expf(s[nt][1] - m0);
            float p2 = __expf(s[nt][2] - m1), p3 = __expf(s[nt][3] - m1);
            l0 += p0 + p1; l1 += p2 + p3;
            Qs[(mrow + g)     * QS_STRIDE + nt * 8 + 2 * t]     = f2tf32(p0);
            Qs[(mrow + g)     * QS_STRIDE + nt * 8 + 2 * t + 1] = f2tf32(p1);
            Qs[(mrow + g + 8) * QS_STRIDE + nt * 8 + 2 * t]     = f2tf32(p2);
            Qs[(mrow + g + 8) * QS_STRIDE + nt * 8 + 2 * t + 1] = f2tf32(p3);
        }
        __syncwarp();

        // O += P @ V
        const int nks = (kb < 4) ? 8 : 1;
        #pragma unroll
        for (int ks = 0; ks < 8; ks++) {
            if (ks >= nks) break;
            uint32_t pf[4];
            pf[0] = Qs[(mrow + g)     * QS_STRIDE + ks * 8 + t];
            pf[1] = Qs[(mrow + g + 8) * QS_STRIDE + ks * 8 + t];
            pf[2] = Qs[(mrow + g)     * QS_STRIDE + ks * 8 + t + 4];
            pf[3] = Qs[(mrow + g + 8) * QS_STRIDE + ks * 8 + t + 4];
            #pragma unroll
            for (int nt = 0; nt < 8; nt++) {
                uint32_t b0 = Vs[(kb * 64 + ks * 8 + t)     * VS_STRIDE + nt * 8 + g];
                uint32_t b1 = Vs[(kb * 64 + ks * 8 + t + 4) * VS_STRIDE + nt * 8 + g];
                mma_tf32(o[nt], pf, b0, b1);
            }
        }
        __syncwarp();
    }

    // finalize
    l0 += __shfl_xor_sync(0xffffffffu, l0, 1);
    l0 += __shfl_xor_sync(0xffffffffu, l0, 2);
    l1 += __shfl_xor_sync(0xffffffffu, l1, 1);
    l1 += __shfl_xor_sync(0xffffffffu, l1, 2);
    const float inv0 = 1.f / l0, inv1 = 1.f / l1;

    const int q0 = chunk * PSZ + half * 128 + mrow + g;
    const int dr0 = order[q0];
    const int dr1 = order[q0 + 8];
    #pragma unroll
    for (int nt = 0; nt < 8; nt++) {
        const int col = head * DHEAD + nt * 8 + 2 * t;
        float2 v0 = make_float2(o[nt][0] * inv0, o[nt][1] * inv0);
        float2 v1 = make_float2(o[nt][2] * inv1, o[nt][3] * inv1);
        *(float2*)(outp + (size_t)dr0 * CHN + col) = v0;
        *(float2*)(outp + (size_t)dr1 * CHN + col) = v1;
    }
}

// ---------------- K3b: cls-query attention (fp32, 1 warp per chunk-head) ---
__global__ __launch_bounds__(256)
void cls_attn_kernel(const float* __restrict__ qkv,
                     const float* __restrict__ cls_qkv,
                     const int* __restrict__ offset,
                     float* __restrict__ cls_out) {
    __shared__ float qs[8][64];
    __shared__ float ps[8][260];

    const int wid  = threadIdx.x >> 5;
    const int lane = threadIdx.x & 31;
    const int pair = blockIdx.x * 8 + wid;
    const int chunk = pair >> 3;
    const int head  = pair & 7;

    const int start = chunk * PSZ;
    const int bid = (start >= offset[0]) + (start >= offset[1]) +
                    (start >= offset[2]) + (start >= offset[3]);
    const float* clsrow = cls_qkv + (size_t)bid * C3;

    qs[wid][lane]      = clsrow[head * DHEAD + lane] * 0.125f;
    qs[wid][lane + 32] = clsrow[head * DHEAD + lane + 32] * 0.125f;
    __syncwarp();

    float mymax = -1e30f;
    for (int j = lane; j < 257; j += 32) {
        const float* kp = (j < 256)
            ? qkv + (size_t)(chunk * PSZ + j) * C3 + CHN + head * DHEAD
            : clsrow + CHN + head * DHEAD;
        float s = 0.f;
        #pragma unroll
        for (int d4 = 0; d4 < 16; d4++) {
            float4 kv = *(const float4*)(kp + d4 * 4);
            s += qs[wid][d4 * 4 + 0] * kv.x + qs[wid][d4 * 4 + 1] * kv.y +
                 qs[wid][d4 * 4 + 2] * kv.z + qs[wid][d4 * 4 + 3] * kv.w;
        }
        ps[wid][j] = s;
        mymax = fmaxf(mymax, s);
    }
    #pragma unroll
    for (int d = 16; d >= 1; d >>= 1)
        mymax = fmaxf(mymax, __shfl_xor_sync(0xffffffffu, mymax, d));

    float sum = 0.f;
    for (int j = lane; j < 257; j += 32) {
        float p = __expf(ps[wid][j] - mymax);
        ps[wid][j] = p;
        sum += p;
    }
    #pragma unroll
    for (int d = 16; d >= 1; d >>= 1)
        sum += __shfl_xor_sync(0xffffffffu, sum, d);
    const float inv = 1.f / sum;
    __syncwarp();

    float a0 = 0.f, a1 = 0.f;
    for (int j = 0; j < 257; j++) {
        const float* vp = (j < 256)
            ? qkv + (size_t)(chunk * PSZ + j) * C3 + 2 * CHN + head * DHEAD
            : clsrow + 2 * CHN + head * DHEAD;
        float p = ps[wid][j];
        a0 += p * vp[lane];
        a1 += p * vp[lane + 32];
    }
    cls_out[(size_t)chunk * CHN + head * DHEAD + lane]      = a0 * inv;
    cls_out[(size_t)chunk * CHN + head * DHEAD + lane + 32] = a1 * inv;
}

// ---------------- K5: cls_feat = per-batch mean of cls_out ------------
__global__ void cls_feat_kernel(const float* __restrict__ cls_out,
                                const int* __restrict__ offset,
                                float* __restrict__ out) {
    int b = blockIdx.x;
    int c = threadIdx.x;
    int o0 = offset[0], o1 = offset[1], o2 = offset[2], o3 = offset[3];
    float s = 0.f, cnt = 0.f;
    for (int ch = 0; ch < NCHUNK; ch++) {
        int start = ch * PSZ;
        int bid = (start >= o0) + (start >= o1) + (start >= o2) + (start >= o3);
        if (bid == b) { s += cls_out[(size_t)ch * CHN + c]; cnt += 1.f; }
    }
    out[(size_t)b * CHN + c] = s / cnt;
}

// ---------------- launch ----------------
extern "C" void kernel_launch(void* const* d_in, const int* in_sizes, int n_in,
                              void* d_out, int out_size) {
    const float* feat       = (const float*)d_in[0];
    const float* cls_tokens = (const float*)d_in[1];
    const float* Wqkv       = (const float*)d_in[2];
    const float* bqkv       = (const float*)d_in[3];
    const float* Wproj      = (const float*)d_in[4];
    const float* bproj      = (const float*)d_in[5];
    const int*   order      = (const int*)d_in[6];
    const int*   inverse    = (const int*)d_in[7];
    const int*   offset     = (const int*)d_in[8];
    float* out = (float*)d_out;

    float *qkv_p, *outp_p, *clsout_p, *clsqkv_p;
    cudaGetSymbolAddress((void**)&qkv_p, g_qkv);
    cudaGetSymbolAddress((void**)&outp_p, g_outp);
    cudaGetSymbolAddress((void**)&clsout_p, g_cls_out);
    cudaGetSymbolAddress((void**)&clsqkv_p, g_cls_qkv);

    cudaFuncSetAttribute(tgemm_kernel<0>, cudaFuncAttributeMaxDynamicSharedMemorySize, GEMM_SMEM);
    cudaFuncSetAttribute(tgemm_kernel<1>, cudaFuncAttributeMaxDynamicSharedMemorySize, GEMM_SMEM);
    cudaFuncSetAttribute(attn_tc_kernel, cudaFuncAttributeMaxDynamicSharedMemorySize, AT_SMEM);

    // K1: cls qkv (tiny)
    cls_qkv_kernel<<<(NBATCH * C3 + 255) / 256, 256>>>(cls_tokens, Wqkv, bqkv, clsqkv_p);

    // K2: qkv = feat @ Wqkv + bqkv, rows scattered by inverse -> serialized order
    tgemm_kernel<0><<<dim3(C3 / 128, NPTS / 128), 256, GEMM_SMEM>>>(
        feat, Wqkv, bqkv, qkv_p, inverse, CHN, CHN, C3, C3);

    // K3: tensor-core flash attention for point queries
    attn_tc_kernel<<<NCHUNK * NHEAD * 2, 256, AT_SMEM>>>(
        qkv_p, clsqkv_p, order, offset, outp_p);

    // K3b: cls-query attention
    cls_attn_kernel<<<NCHUNK * NHEAD / 8, 256>>>(qkv_p, clsqkv_p, offset, clsout_p);

    // K4: feat_out = outp @ Wproj + bproj
    tgemm_kernel<1><<<dim3(CHN / 128, NPTS / 128), 256, GEMM_SMEM>>>(
        outp_p, Wproj, bproj, out, nullptr, CHN, CHN, CHN, CHN);

    // K5: cls_feat
    cls_feat_kernel<<<NBATCH, CHN>>>(clsout_p, offset, out + (size_t)NPTS * CHN);
}

// round 6
// speedup vs baseline: 3.7404x; 1.1161x over previous
#include <cuda_runtime.h>
#include <cstdint>
#include <cstddef>

#define NPTS   65536
#define CHN    512
#define C3     1536
#define PSZ    256
#define NHEAD  8
#define DHEAD  64
#define NBATCH 4
#define NCHUNK (NPTS / PSZ)   // 256

// ---------------- scratch (device globals: allocation-free) ----------------
__device__ float g_qkv[(size_t)NPTS * C3];       // serialized-order qkv
__device__ float g_outp[(size_t)NPTS * CHN];     // attention out, original order
__device__ float g_cls_out[NCHUNK * CHN];        // per-chunk cls attention output
__device__ float g_cls_qkv[NBATCH * C3];         // cls token qkv per batch

__device__ __forceinline__ uint32_t f2tf32(float f) {
    uint32_t u;
    asm("cvt.rna.tf32.f32 %0, %1;" : "=r"(u) : "f"(f));
    return u;
}

__device__ __forceinline__ void mma_tf32(float* c, const uint32_t* a,
                                         uint32_t b0, uint32_t b1) {
    asm volatile(
        "mma.sync.aligned.m16n8k8.row.col.f32.tf32.tf32.f32 "
        "{%0,%1,%2,%3}, {%4,%5,%6,%7}, {%8,%9}, {%0,%1,%2,%3};"
        : "+f"(c[0]), "+f"(c[1]), "+f"(c[2]), "+f"(c[3])
        : "r"(a[0]), "r"(a[1]), "r"(a[2]), "r"(a[3]), "r"(b0), "r"(b1));
}

__device__ __forceinline__ void cp16(uint32_t smem_addr, const void* gptr) {
    asm volatile("cp.async.cg.shared.global [%0], [%1], 16;"
                 :: "r"(smem_addr), "l"(gptr) : "memory");
}
__device__ __forceinline__ void cp_commit() {
    asm volatile("cp.async.commit_group;" ::: "memory");
}
template <int N>
__device__ __forceinline__ void cp_wait() {
    asm volatile("cp.async.wait_group %0;" :: "n"(N) : "memory");
}

// ---------------- K1: cls_qkv = cls_tokens @ Wqkv + bqkv ----------------
__global__ void cls_qkv_kernel(const float* __restrict__ cls_tokens,
                               const float* __restrict__ Wqkv,
                               const float* __restrict__ bqkv,
                               float* __restrict__ cls_qkv) {
    int idx = blockIdx.x * blockDim.x + threadIdx.x;
    if (idx >= NBATCH * C3) return;
    int b = idx / C3, o = idx % C3;
    float s = bqkv[o];
    #pragma unroll 4
    for (int k = 0; k < CHN; k++)
        s += cls_tokens[b * CHN + k] * Wqkv[(size_t)k * C3 + o];
    cls_qkv[idx] = s;
}

// ------ tf32 GEMM: 128x128x32, 256 thr, cp.async 3-stage, 2 CTAs/SM -------
#define AS_STRIDE 36
#define BS_STRIDE 136
#define AS_BUF (128 * AS_STRIDE)          // 4608 floats
#define BS_BUF (32 * BS_STRIDE)           // 4352 floats
#define NSTAGE 3
#define GEMM_SMEM (NSTAGE * (AS_BUF + BS_BUF) * 4)   // 107520 bytes

template <int MODE>
__global__ __launch_bounds__(256, 2)
void tgemm_kernel(const float* __restrict__ A, const float* __restrict__ B,
                  const float* __restrict__ bias, float* __restrict__ Cout,
                  const int* __restrict__ rowmap,
                  int Kdim, int lda, int ldb, int ldc) {
    extern __shared__ float smf[];
    float* As = smf;                       // [3][128][36]  fp32
    float* Bs = smf + NSTAGE * AS_BUF;     // [3][32][136]  fp32

    const int tid  = threadIdx.x;
    const int lane = tid & 31;
    const int warp = tid >> 5;
    const int wm   = warp >> 2;
    const int wn   = warp & 3;
    const int g    = lane >> 2;
    const int t    = lane & 3;

    const int a_row = tid >> 1;
    const int a_k0  = (tid & 1) * 16;
    const float* Aptr = A + (size_t)(blockIdx.y * 128 + a_row) * lda + a_k0;
    const float* Bbase = B + blockIdx.x * 128;

    const uint32_t as_s = (uint32_t)__cvta_generic_to_shared(As + a_row * AS_STRIDE + a_k0);
    const int b_r  = tid >> 5;          // base row for i=0 slice: rows advance by 8
    const int b_c4 = tid & 31;
    const uint32_t bs_s = (uint32_t)__cvta_generic_to_shared(Bs + b_r * BS_STRIDE + b_c4 * 4);

    auto issue = [&](int kt, int buf) {
        const float* ag = Aptr + kt * 32;
        uint32_t ad = as_s + buf * (AS_BUF * 4);
        cp16(ad,      ag);
        cp16(ad + 16, ag + 4);
        cp16(ad + 32, ag + 8);
        cp16(ad + 48, ag + 12);
        const float* bg = Bbase + (size_t)(kt * 32 + b_r) * ldb + b_c4 * 4;
        uint32_t bd = bs_s + buf * (BS_BUF * 4);
        #pragma unroll
        for (int i = 0; i < 4; i++)
            cp16(bd + i * (8 * BS_STRIDE * 4), bg + (size_t)(8 * i) * ldb);
    };

    const int nk = Kdim >> 5;
    issue(0, 0); cp_commit();
    issue(1, 1); cp_commit();

    float c[4][4][4];
    #pragma unroll
    for (int mi = 0; mi < 4; mi++)
        #pragma unroll
        for (int ni = 0; ni < 4; ni++)
            #pragma unroll
            for (int r = 0; r < 4; r++) c[mi][ni][r] = 0.f;

    for (int kt = 0; kt < nk; kt++) {
        const int cur = kt % NSTAGE;
        if (kt + 1 < nk) cp_wait<1>(); else cp_wait<0>();
        __syncthreads();
        if (kt + 2 < nk) { issue(kt + 2, (kt + 2) % NSTAGE); cp_commit(); }

        const float* asb = As + cur * AS_BUF;
        const float* bsb = Bs + cur * BS_BUF;
        #pragma unroll
        for (int ks = 0; ks < 4; ks++) {
            const int k0 = ks * 8;
            uint32_t af[4][4], bf[4][2];
            #pragma unroll
            for (int mi = 0; mi < 4; mi++) {
                const int row = wm * 64 + mi * 16 + g;
                af[mi][0] = f2tf32(asb[(row)     * AS_STRIDE + k0 + t]);
                af[mi][1] = f2tf32(asb[(row + 8) * AS_STRIDE + k0 + t]);
                af[mi][2] = f2tf32(asb[(row)     * AS_STRIDE + k0 + t + 4]);
                af[mi][3] = f2tf32(asb[(row + 8) * AS_STRIDE + k0 + t + 4]);
            }
            #pragma unroll
            for (int ni = 0; ni < 4; ni++) {
                const int col = wn * 32 + ni * 8 + g;
                bf[ni][0] = f2tf32(bsb[(k0 + t)     * BS_STRIDE + col]);
                bf[ni][1] = f2tf32(bsb[(k0 + t + 4) * BS_STRIDE + col]);
            }
            #pragma unroll
            for (int mi = 0; mi < 4; mi++)
                #pragma unroll
                for (int ni = 0; ni < 4; ni++)
                    mma_tf32(c[mi][ni], af[mi], bf[ni][0], bf[ni][1]);
        }
        __syncthreads();
    }

    float2 bv[4];
    #pragma unroll
    for (int ni = 0; ni < 4; ni++)
        bv[ni] = *(const float2*)&bias[blockIdx.x * 128 + wn * 32 + ni * 8 + t * 2];

    #pragma unroll
    for (int mi = 0; mi < 4; mi++) {
        const int m0 = blockIdx.y * 128 + wm * 64 + mi * 16 + g;
        const int r0 = (MODE == 0) ? rowmap[m0]     : m0;
        const int r1 = (MODE == 0) ? rowmap[m0 + 8] : m0 + 8;
        #pragma unroll
        for (int ni = 0; ni < 4; ni++) {
            const int col = blockIdx.x * 128 + wn * 32 + ni * 8 + t * 2;
            float2 v0 = make_float2(c[mi][ni][0] + bv[ni].x, c[mi][ni][1] + bv[ni].y);
            float2 v1 = make_float2(c[mi][ni][2] + bv[ni].x, c[mi][ni][3] + bv[ni].y);
            *(float2*)(Cout + (size_t)r0 * ldc + col) = v0;
            *(float2*)(Cout + (size_t)r1 * ldc + col) = v1;
        }
    }
}

// ---------------- K3: tensor-core flash attention (point queries) ----------
#define KT_STRIDE 264
#define VS_STRIDE 72
#define QS_STRIDE 72
#define KT_WORDS (64 * KT_STRIDE)
#define VS_WORDS (264 * VS_STRIDE)
#define QS_WORDS (128 * QS_STRIDE)
#define AT_SMEM ((KT_WORDS + VS_WORDS + QS_WORDS) * 4)   // 180480 bytes

__global__ __launch_bounds__(256)
void attn_tc_kernel(const float* __restrict__ qkv,
                    const float* __restrict__ cls_qkv,
                    const int* __restrict__ order,
                    const int* __restrict__ offset,
                    float* __restrict__ outp) {
    extern __shared__ uint32_t sm[];
    uint32_t* Kt = sm;
    uint32_t* Vs = sm + KT_WORDS;
    uint32_t* Qs = sm + KT_WORDS + VS_WORDS;

    const int bx    = blockIdx.x;
    const int chunk = bx >> 4;
    const int head  = (bx >> 1) & 7;
    const int half  = bx & 1;
    const int tid   = threadIdx.x;

    const int start = chunk * PSZ;
    const int bid = (start >= offset[0]) + (start >= offset[1]) +
                    (start >= offset[2]) + (start >= offset[3]);
    const float* clsrow = cls_qkv + (size_t)bid * C3;

    for (int e = tid; e < 64 * 7; e += 256) {
        int d = e / 7, k = e % 7;
        Kt[d * KT_STRIDE + 257 + k] = 0;
    }
    for (int e = tid; e < 7 * VS_STRIDE; e += 256)
        Vs[257 * VS_STRIDE + e] = 0;

    for (int key = tid; key < 257; key += 256) {
        const float* base = (key < 256)
            ? qkv + (size_t)(chunk * PSZ + key) * C3 : clsrow;
        #pragma unroll
        for (int d4 = 0; d4 < 16; d4++) {
            float4 kv = *(const float4*)(base + CHN + head * DHEAD + d4 * 4);
            Kt[(d4 * 4 + 0) * KT_STRIDE + key] = f2tf32(kv.x);
            Kt[(d4 * 4 + 1) * KT_STRIDE + key] = f2tf32(kv.y);
            Kt[(d4 * 4 + 2) * KT_STRIDE + key] = f2tf32(kv.z);
            Kt[(d4 * 4 + 3) * KT_STRIDE + key] = f2tf32(kv.w);
        }
    }
    for (int e = tid; e < 257 * 16; e += 256) {
        int key = e >> 4, d4 = e & 15;
        const float* base = (key < 256)
            ? qkv + (size_t)(chunk * PSZ + key) * C3 : clsrow;
        float4 vv = *(const float4*)(base + 2 * CHN + head * DHEAD + d4 * 4);
        uint32_t* dst = Vs + key * VS_STRIDE + d4 * 4;
        dst[0] = f2tf32(vv.x); dst[1] = f2tf32(vv.y);
        dst[2] = f2tf32(vv.z); dst[3] = f2tf32(vv.w);
    }
    for (int e = tid; e < 128 * 16; e += 256) {
        int i = e >> 4, d4 = e & 15;
        const float* base = qkv + (size_t)(chunk * PSZ + half * 128 + i) * C3;
        float4 qv = *(const float4*)(base + head * DHEAD + d4 * 4);
        uint32_t* dst = Qs + i * QS_STRIDE + d4 * 4;
        dst[0] = f2tf32(qv.x * 0.125f); dst[1] = f2tf32(qv.y * 0.125f);
        dst[2] = f2tf32(qv.z * 0.125f); dst[3] = f2tf32(qv.w * 0.125f);
    }
    __syncthreads();

    const int warp = tid >> 5, lane = tid & 31;
    const int g = lane >> 2, t = lane & 3;
    const int mrow = warp * 16;

    uint32_t qf[8][4];
    #pragma unroll
    for (int ks = 0; ks < 8; ks++) {
        qf[ks][0] = Qs[(mrow + g)     * QS_STRIDE + ks * 8 + t];
        qf[ks][1] = Qs[(mrow + g + 8) * QS_STRIDE + ks * 8 + t];
        qf[ks][2] = Qs[(mrow + g)     * QS_STRIDE + ks * 8 + t + 4];
        qf[ks][3] = Qs[(mrow + g + 8) * QS_STRIDE + ks * 8 + t + 4];
    }
    __syncwarp();

    float o[8][4];
    #pragma unroll
    for (int nt = 0; nt < 8; nt++)
        #pragma unroll
        for (int r = 0; r < 4; r++) o[nt][r] = 0.f;
    float m0 = -1e30f, m1 = -1e30f, l0 = 0.f, l1 = 0.f;

    for (int kb = 0; kb < 5; kb++) {
        const int nnt = (kb < 4) ? 8 : 1;
        float s[8][4];
        #pragma unroll
        for (int nt = 0; nt < 8; nt++)
            #pragma unroll
            for (int r = 0; r < 4; r++) s[nt][r] = 0.f;

        #pragma unroll
        for (int ks = 0; ks < 8; ks++) {
            #pragma unroll
            for (int nt = 0; nt < 8; nt++) {
                if (nt >= nnt) break;
                uint32_t b0 = Kt[(ks * 8 + t)     * KT_STRIDE + kb * 64 + nt * 8 + g];
                uint32_t b1 = Kt[(ks * 8 + t + 4) * KT_STRIDE + kb * 64 + nt * 8 + g];
                mma_tf32(s[nt], qf[ks], b0, b1);
            }
        }
        if (kb == 4) {
            if (t != 0) { s[0][0] = -1e30f; s[0][2] = -1e30f; }
            s[0][1] = -1e30f; s[0][3] = -1e30f;
        }

        float mx0 = -1e30f, mx1 = -1e30f;
        #pragma unroll
        for (int nt = 0; nt < 8; nt++) {
            if (nt >= nnt) break;
            mx0 = fmaxf(mx0, fmaxf(s[nt][0], s[nt][1]));
            mx1 = fmaxf(mx1, fmaxf(s[nt][2], s[nt][3]));
        }
        mx0 = fmaxf(mx0, __shfl_xor_sync(0xffffffffu, mx0, 1));
        mx0 = fmaxf(mx0, __shfl_xor_sync(0xffffffffu, mx0, 2));
        mx1 = fmaxf(mx1, __shfl_xor_sync(0xffffffffu, mx1, 1));
        mx1 = fmaxf(mx1, __shfl_xor_sync(0xffffffffu, mx1, 2));
        float nm0 = fmaxf(m0, mx0), nm1 = fmaxf(m1, mx1);
        float f0 = __expf(m0 - nm0), f1 = __expf(m1 - nm1);
        m0 = nm0; m1 = nm1; l0 *= f0; l1 *= f1;
        #pragma unroll
        for (int nt = 0; nt < 8; nt++) {
            o[nt][0] *= f0; o[nt][1] *= f0;
            o[nt][2] *= f1; o[nt][3] *= f1;
        }
        #pragma unroll
        for (int nt = 0; nt < 8; nt++) {
            if (nt >= nnt) break;
            float p0 = __expf(s[nt][0] - m0), p1 = __expf(s[nt][1] - m0);
            float p2 = __expf(s[nt][2] - m1), p3 = __expf(s[nt][3] - m1);
            l0 += p0 + p1; l1 += p2 + p3;
            Qs[(mrow + g)     * QS_STRIDE + nt * 8 + 2 * t]     = f2tf32(p0);
            Qs[(mrow + g)     * QS_STRIDE + nt * 8 + 2 * t + 1] = f2tf32(p1);
            Qs[(mrow + g + 8) * QS_STRIDE + nt * 8 + 2 * t]     = f2tf32(p2);
            Qs[(mrow + g + 8) * QS_STRIDE + nt * 8 + 2 * t + 1] = f2tf32(p3);
        }
        __syncwarp();

        const int nks = (kb < 4) ? 8 : 1;
        #pragma unroll
        for (int ks = 0; ks < 8; ks++) {
            if (ks >= nks) break;
            uint32_t pf[4];
            pf[0] = Qs[(mrow + g)     * QS_STRIDE + ks * 8 + t];
            pf[1] = Qs[(mrow + g + 8) * QS_STRIDE + ks * 8 + t];
            pf[2] = Qs[(mrow + g)     * QS_STRIDE + ks * 8 + t + 4];
            pf[3] = Qs[(mrow + g + 8) * QS_STRIDE + ks * 8 + t + 4];
            #pragma unroll
            for (int nt = 0; nt < 8; nt++) {
                uint32_t b0 = Vs[(kb * 64 + ks * 8 + t)     * VS_STRIDE + nt * 8 + g];
                uint32_t b1 = Vs[(kb * 64 + ks * 8 + t + 4) * VS_STRIDE + nt * 8 + g];
                mma_tf32(o[nt], pf, b0, b1);
            }
        }
        __syncwarp();
    }

    l0 += __shfl_xor_sync(0xffffffffu, l0, 1);
    l0 += __shfl_xor_sync(0xffffffffu, l0, 2);
    l1 += __shfl_xor_sync(0xffffffffu, l1, 1);
    l1 += __shfl_xor_sync(0xffffffffu, l1, 2);
    const float inv0 = 1.f / l0, inv1 = 1.f / l1;

    const int q0 = chunk * PSZ + half * 128 + mrow + g;
    const int dr0 = order[q0];
    const int dr1 = order[q0 + 8];
    #pragma unroll
    for (int nt = 0; nt < 8; nt++) {
        const int col = head * DHEAD + nt * 8 + 2 * t;
        float2 v0 = make_float2(o[nt][0] * inv0, o[nt][1] * inv0);
        float2 v1 = make_float2(o[nt][2] * inv1, o[nt][3] * inv1);
        *(float2*)(outp + (size_t)dr0 * CHN + col) = v0;
        *(float2*)(outp + (size_t)dr1 * CHN + col) = v1;
    }
}

// ---------------- K3b: cls-query attention, one block per chunk ------------
__global__ __launch_bounds__(256)
void cls_attn2_kernel(const float* __restrict__ qkv,
                      const float* __restrict__ cls_qkv,
                      const int* __restrict__ offset,
                      float* __restrict__ cls_out) {
    __shared__ float qs[8][68];    // padded: bank = (4h + d) % 32, conflict-free
    __shared__ float ps[8][260];
    __shared__ float sinv[8];

    const int chunk = blockIdx.x;
    const int tid   = threadIdx.x;
    const int start = chunk * PSZ;
    const int bid = (start >= offset[0]) + (start >= offset[1]) +
                    (start >= offset[2]) + (start >= offset[3]);
    const float* clsrow = cls_qkv + (size_t)bid * C3;

    for (int e = tid; e < 512; e += 256)
        qs[e >> 6][e & 63] = clsrow[e] * 0.125f;
    __syncthreads();

    // scores: idx -> (j = idx>>3, h = idx&7); 8 threads cover one K row (2KB)
    for (int idx = tid; idx < 8 * 257; idx += 256) {
        const int j = idx >> 3, h = idx & 7;
        const float* kp = (j < 256)
            ? qkv + (size_t)(chunk * PSZ + j) * C3 + CHN + h * DHEAD
            : clsrow + CHN + h * DHEAD;
        float s = 0.f;
        #pragma unroll
        for (int d4 = 0; d4 < 16; d4++) {
            float4 kv = *(const float4*)(kp + d4 * 4);
            s += qs[h][d4 * 4 + 0] * kv.x + qs[h][d4 * 4 + 1] * kv.y +
                 qs[h][d4 * 4 + 2] * kv.z + qs[h][d4 * 4 + 3] * kv.w;
        }
        ps[h][j] = s;
    }
    __syncthreads();

    // softmax: warp w handles head w
    const int w = tid >> 5, lane = tid & 31;
    {
        float mx = -1e30f;
        for (int j = lane; j < 257; j += 32) mx = fmaxf(mx, ps[w][j]);
        #pragma unroll
        for (int d = 16; d >= 1; d >>= 1)
            mx = fmaxf(mx, __shfl_xor_sync(0xffffffffu, mx, d));
        float sum = 0.f;
        for (int j = lane; j < 257; j += 32) {
            float p = __expf(ps[w][j] - mx);
            ps[w][j] = p;
            sum += p;
        }
        #pragma unroll
        for (int d = 16; d >= 1; d >>= 1)
            sum += __shfl_xor_sync(0xffffffffu, sum, d);
        if (lane == 0) sinv[w] = 1.f / sum;
    }
    __syncthreads();

    // V accumulation: thread owns cols (2t, 2t+1); rows streamed coalesced
    const int h = tid >> 5;   // = (2*tid)>>6, warp-uniform -> ps broadcast
    float a0 = 0.f, a1 = 0.f;
    const float* vb = qkv + (size_t)chunk * PSZ * C3 + 2 * CHN + 2 * tid;
    #pragma unroll 4
    for (int j = 0; j < 256; j++) {
        float2 v = *(const float2*)(vb + (size_t)j * C3);
        float p = ps[h][j];
        a0 += p * v.x; a1 += p * v.y;
    }
    {
        float2 v = *(const float2*)(clsrow + 2 * CHN + 2 * tid);
        float p = ps[h][256];
        a0 += p * v.x; a1 += p * v.y;
    }
    const float inv = sinv[h];
    cls_out[(size_t)chunk * CHN + 2 * tid]     = a0 * inv;
    cls_out[(size_t)chunk * CHN + 2 * tid + 1] = a1 * inv;
}

// ---------------- K5: cls_feat = per-batch mean of cls_out ------------
__global__ void cls_feat_kernel(const float* __restrict__ cls_out,
                                const int* __restrict__ offset,
                                float* __restrict__ out) {
    int b = blockIdx.x;
    int c = threadIdx.x;
    int o0 = offset[0], o1 = offset[1], o2 = offset[2], o3 = offset[3];
    float s = 0.f, cnt = 0.f;
    for (int ch = 0; ch < NCHUNK; ch++) {
        int start = ch * PSZ;
        int bid = (start >= o0) + (start >= o1) + (start >= o2) + (start >= o3);
        if (bid == b) { s += cls_out[(size_t)ch * CHN + c]; cnt += 1.f; }
    }
    out[(size_t)b * CHN + c] = s / cnt;
}

// ---------------- launch ----------------
extern "C" void kernel_launch(void* const* d_in, const int* in_sizes, int n_in,
                              void* d_out, int out_size) {
    const float* feat       = (const float*)d_in[0];
    const float* cls_tokens = (const float*)d_in[1];
    const float* Wqkv       = (const float*)d_in[2];
    const float* bqkv       = (const float*)d_in[3];
    const float* Wproj      = (const float*)d_in[4];
    const float* bproj      = (const float*)d_in[5];
    const int*   order      = (const int*)d_in[6];
    const int*   inverse    = (const int*)d_in[7];
    const int*   offset     = (const int*)d_in[8];
    float* out = (float*)d_out;

    float *qkv_p, *outp_p, *clsout_p, *clsqkv_p;
    cudaGetSymbolAddress((void**)&qkv_p, g_qkv);
    cudaGetSymbolAddress((void**)&outp_p, g_outp);
    cudaGetSymbolAddress((void**)&clsout_p, g_cls_out);
    cudaGetSymbolAddress((void**)&clsqkv_p, g_cls_qkv);

    cudaFuncSetAttribute(tgemm_kernel<0>, cudaFuncAttributeMaxDynamicSharedMemorySize, GEMM_SMEM);
    cudaFuncSetAttribute(tgemm_kernel<1>, cudaFuncAttributeMaxDynamicSharedMemorySize, GEMM_SMEM);
    cudaFuncSetAttribute(attn_tc_kernel, cudaFuncAttributeMaxDynamicSharedMemorySize, AT_SMEM);

    // K1: cls qkv (tiny)
    cls_qkv_kernel<<<(NBATCH * C3 + 255) / 256, 256>>>(cls_tokens, Wqkv, bqkv, clsqkv_p);

    // K2: qkv = feat @ Wqkv + bqkv, rows scattered by inverse -> serialized order
    tgemm_kernel<0><<<dim3(C3 / 128, NPTS / 128), 256, GEMM_SMEM>>>(
        feat, Wqkv, bqkv, qkv_p, inverse, CHN, CHN, C3, C3);

    // K3: tensor-core flash attention for point queries
    attn_tc_kernel<<<NCHUNK * NHEAD * 2, 256, AT_SMEM>>>(
        qkv_p, clsqkv_p, order, offset, outp_p);

    // K3b: cls-query attention (per-chunk, coalesced)
    cls_attn2_kernel<<<NCHUNK, 256>>>(qkv_p, clsqkv_p, offset, clsout_p);

    // K4: feat_out = outp @ Wproj + bproj
    tgemm_kernel<1><<<dim3(CHN / 128, NPTS / 128), 256, GEMM_SMEM>>>(
        outp_p, Wproj, bproj, out, nullptr, CHN, CHN, CHN, CHN);

    // K5: cls_feat
    cls_feat_kernel<<<NBATCH, CHN>>>(clsout_p, offset, out + (size_t)NPTS * CHN);
}

// round 7
// speedup vs baseline: 3.7720x; 1.0084x over previous
#include <cuda_runtime.h>
#include <cstdint>
#include <cstddef>

#define NPTS   65536
#define CHN    512
#define C3     1536
#define PSZ    256
#define NHEAD  8
#define DHEAD  64
#define NBATCH 4
#define NCHUNK (NPTS / PSZ)   // 256

// ---------------- scratch (device globals: allocation-free) ----------------
__device__ float g_qkv[(size_t)NPTS * C3];       // serialized-order qkv
__device__ float g_outp[(size_t)NPTS * CHN];     // attention out, original order
__device__ float g_cls_out[NCHUNK * CHN];        // per-chunk cls attention output
__device__ float g_cls_qkv[NBATCH * C3];         // cls token qkv per batch

__device__ __forceinline__ uint32_t f2tf32(float f) {
    uint32_t u;
    asm("cvt.rna.tf32.f32 %0, %1;" : "=r"(u) : "f"(f));
    return u;
}

__device__ __forceinline__ void mma_tf32(float* c, const uint32_t* a,
                                         uint32_t b0, uint32_t b1) {
    asm volatile(
        "mma.sync.aligned.m16n8k8.row.col.f32.tf32.tf32.f32 "
        "{%0,%1,%2,%3}, {%4,%5,%6,%7}, {%8,%9}, {%0,%1,%2,%3};"
        : "+f"(c[0]), "+f"(c[1]), "+f"(c[2]), "+f"(c[3])
        : "r"(a[0]), "r"(a[1]), "r"(a[2]), "r"(a[3]), "r"(b0), "r"(b1));
}

__device__ __forceinline__ void cp16(uint32_t smem_addr, const void* gptr) {
    asm volatile("cp.async.cg.shared.global [%0], [%1], 16;"
                 :: "r"(smem_addr), "l"(gptr) : "memory");
}
__device__ __forceinline__ void cp_commit() {
    asm volatile("cp.async.commit_group;" ::: "memory");
}
template <int N>
__device__ __forceinline__ void cp_wait() {
    asm volatile("cp.async.wait_group %0;" :: "n"(N) : "memory");
}

// ---------------- K1: cls_qkv = cls_tokens @ Wqkv + bqkv ----------------
__global__ void cls_qkv_kernel(const float* __restrict__ cls_tokens,
                               const float* __restrict__ Wqkv,
                               const float* __restrict__ bqkv,
                               float* __restrict__ cls_qkv) {
    int idx = blockIdx.x * blockDim.x + threadIdx.x;
    if (idx >= NBATCH * C3) return;
    int b = idx / C3, o = idx % C3;
    float s = bqkv[o];
    #pragma unroll 4
    for (int k = 0; k < CHN; k++)
        s += cls_tokens[b * CHN + k] * Wqkv[(size_t)k * C3 + o];
    cls_qkv[idx] = s;
}

// ------ tf32 GEMM: 128x128x32, 256 thr, cp.async 3-stage, 2 CTAs/SM -------
#define AS_STRIDE 36
#define BS_STRIDE 136
#define AS_BUF (128 * AS_STRIDE)          // 4608 floats
#define BS_BUF (32 * BS_STRIDE)           // 4352 floats
#define NSTAGE 3
#define GEMM_SMEM (NSTAGE * (AS_BUF + BS_BUF) * 4)   // 107520 bytes

template <int MODE>
__global__ __launch_bounds__(256, 2)
void tgemm_kernel(const float* __restrict__ A, const float* __restrict__ B,
                  const float* __restrict__ bias, float* __restrict__ Cout,
                  const int* __restrict__ rowmap,
                  int Kdim, int lda, int ldb, int ldc) {
    extern __shared__ float smf[];
    float* As = smf;                       // [3][128][36]  fp32
    float* Bs = smf + NSTAGE * AS_BUF;     // [3][32][136]  fp32

    const int tid  = threadIdx.x;
    const int lane = tid & 31;
    const int warp = tid >> 5;
    const int wm   = warp >> 2;
    const int wn   = warp & 3;
    const int g    = lane >> 2;
    const int t    = lane & 3;

    const int a_row = tid >> 1;
    const int a_k0  = (tid & 1) * 16;
    const float* Aptr = A + (size_t)(blockIdx.y * 128 + a_row) * lda + a_k0;
    const float* Bbase = B + blockIdx.x * 128;

    const uint32_t as_s = (uint32_t)__cvta_generic_to_shared(As + a_row * AS_STRIDE + a_k0);
    const int b_r  = tid >> 5;
    const int b_c4 = tid & 31;
    const uint32_t bs_s = (uint32_t)__cvta_generic_to_shared(Bs + b_r * BS_STRIDE + b_c4 * 4);

    auto issue = [&](int kt, int buf) {
        const float* ag = Aptr + kt * 32;
        uint32_t ad = as_s + buf * (AS_BUF * 4);
        cp16(ad,      ag);
        cp16(ad + 16, ag + 4);
        cp16(ad + 32, ag + 8);
        cp16(ad + 48, ag + 12);
        const float* bg = Bbase + (size_t)(kt * 32 + b_r) * ldb + b_c4 * 4;
        uint32_t bd = bs_s + buf * (BS_BUF * 4);
        #pragma unroll
        for (int i = 0; i < 4; i++)
            cp16(bd + i * (8 * BS_STRIDE * 4), bg + (size_t)(8 * i) * ldb);
    };

    const int nk = Kdim >> 5;
    issue(0, 0); cp_commit();
    issue(1, 1); cp_commit();

    float c[4][4][4];
    #pragma unroll
    for (int mi = 0; mi < 4; mi++)
        #pragma unroll
        for (int ni = 0; ni < 4; ni++)
            #pragma unroll
            for (int r = 0; r < 4; r++) c[mi][ni][r] = 0.f;

    for (int kt = 0; kt < nk; kt++) {
        const int cur = kt % NSTAGE;
        if (kt + 1 < nk) cp_wait<1>(); else cp_wait<0>();
        __syncthreads();   // stage-kt data visible; prior-iter readers of the
                           // buffer we are about to overwrite are also done
        if (kt + 2 < nk) { issue(kt + 2, (kt + 2) % NSTAGE); cp_commit(); }

        const float* asb = As + cur * AS_BUF;
        const float* bsb = Bs + cur * BS_BUF;
        #pragma unroll
        for (int ks = 0; ks < 4; ks++) {
            const int k0 = ks * 8;
            uint32_t af[4][4], bf[4][2];
            #pragma unroll
            for (int mi = 0; mi < 4; mi++) {
                const int row = wm * 64 + mi * 16 + g;
                af[mi][0] = f2tf32(asb[(row)     * AS_STRIDE + k0 + t]);
                af[mi][1] = f2tf32(asb[(row + 8) * AS_STRIDE + k0 + t]);
                af[mi][2] = f2tf32(asb[(row)     * AS_STRIDE + k0 + t + 4]);
                af[mi][3] = f2tf32(asb[(row + 8) * AS_STRIDE + k0 + t + 4]);
            }
            #pragma unroll
            for (int ni = 0; ni < 4; ni++) {
                const int col = wn * 32 + ni * 8 + g;
                bf[ni][0] = f2tf32(bsb[(k0 + t)     * BS_STRIDE + col]);
                bf[ni][1] = f2tf32(bsb[(k0 + t + 4) * BS_STRIDE + col]);
            }
            #pragma unroll
            for (int mi = 0; mi < 4; mi++)
                #pragma unroll
                for (int ni = 0; ni < 4; ni++)
                    mma_tf32(c[mi][ni], af[mi], bf[ni][0], bf[ni][1]);
        }
        // no trailing barrier: next iteration's top barrier fences these reads
        // before any cp.async overwrites this buffer (3-stage ring).
    }

    float2 bv[4];
    #pragma unroll
    for (int ni = 0; ni < 4; ni++)
        bv[ni] = *(const float2*)&bias[blockIdx.x * 128 + wn * 32 + ni * 8 + t * 2];

    #pragma unroll
    for (int mi = 0; mi < 4; mi++) {
        const int m0 = blockIdx.y * 128 + wm * 64 + mi * 16 + g;
        const int r0 = (MODE == 0) ? rowmap[m0]     : m0;
        const int r1 = (MODE == 0) ? rowmap[m0 + 8] : m0 + 8;
        #pragma unroll
        for (int ni = 0; ni < 4; ni++) {
            const int col = blockIdx.x * 128 + wn * 32 + ni * 8 + t * 2;
            float2 v0 = make_float2(c[mi][ni][0] + bv[ni].x, c[mi][ni][1] + bv[ni].y);
            float2 v1 = make_float2(c[mi][ni][2] + bv[ni].x, c[mi][ni][3] + bv[ni].y);
            *(float2*)(Cout + (size_t)r0 * ldc + col) = v0;
            *(float2*)(Cout + (size_t)r1 * ldc + col) = v1;
        }
    }
}

// ---------------- K3: tensor-core flash attention (point queries) ----------
// Block = 256 thr, one block per (chunk, head, half-of-128-queries).
// half==0 blocks additionally compute the cls-query attention for this
// (chunk, head) from the K/V tiles already resident in smem.
#define KT_STRIDE 264
#define VS_STRIDE 72
#define QS_STRIDE 72
#define KT_WORDS (64 * KT_STRIDE)
#define VS_WORDS (264 * VS_STRIDE)
#define QS_WORDS (128 * QS_STRIDE)
#define AT_SMEM ((KT_WORDS + VS_WORDS + QS_WORDS) * 4)   // 180480 bytes

__global__ __launch_bounds__(256)
void attn_tc_kernel(const float* __restrict__ qkv,
                    const float* __restrict__ cls_qkv,
                    const int* __restrict__ order,
                    const int* __restrict__ offset,
                    float* __restrict__ outp,
                    float* __restrict__ cls_out) {
    extern __shared__ uint32_t sm[];
    uint32_t* Kt = sm;
    uint32_t* Vs = sm + KT_WORDS;
    uint32_t* Qs = sm + KT_WORDS + VS_WORDS;

    __shared__ float cq[64];        // cls query (scaled)
    __shared__ float cps[257];      // cls scores / probs
    __shared__ float cpart[256];    // cls PV partials
    __shared__ float cstat[2];      // max, inv-sum

    const int bx    = blockIdx.x;
    const int chunk = bx >> 4;
    const int head  = (bx >> 1) & 7;
    const int half  = bx & 1;
    const int tid   = threadIdx.x;

    const int start = chunk * PSZ;
    const int bid = (start >= offset[0]) + (start >= offset[1]) +
                    (start >= offset[2]) + (start >= offset[3]);
    const float* clsrow = cls_qkv + (size_t)bid * C3;

    for (int e = tid; e < 64 * 7; e += 256) {
        int d = e / 7, k = e % 7;
        Kt[d * KT_STRIDE + 257 + k] = 0;
    }
    for (int e = tid; e < 7 * VS_STRIDE; e += 256)
        Vs[257 * VS_STRIDE + e] = 0;

    for (int key = tid; key < 257; key += 256) {
        const float* base = (key < 256)
            ? qkv + (size_t)(chunk * PSZ + key) * C3 : clsrow;
        #pragma unroll
        for (int d4 = 0; d4 < 16; d4++) {
            float4 kv = *(const float4*)(base + CHN + head * DHEAD + d4 * 4);
            Kt[(d4 * 4 + 0) * KT_STRIDE + key] = f2tf32(kv.x);
            Kt[(d4 * 4 + 1) * KT_STRIDE + key] = f2tf32(kv.y);
            Kt[(d4 * 4 + 2) * KT_STRIDE + key] = f2tf32(kv.z);
            Kt[(d4 * 4 + 3) * KT_STRIDE + key] = f2tf32(kv.w);
        }
    }
    for (int e = tid; e < 257 * 16; e += 256) {
        int key = e >> 4, d4 = e & 15;
        const float* base = (key < 256)
            ? qkv + (size_t)(chunk * PSZ + key) * C3 : clsrow;
        float4 vv = *(const float4*)(base + 2 * CHN + head * DHEAD + d4 * 4);
        uint32_t* dst = Vs + key * VS_STRIDE + d4 * 4;
        dst[0] = f2tf32(vv.x); dst[1] = f2tf32(vv.y);
        dst[2] = f2tf32(vv.z); dst[3] = f2tf32(vv.w);
    }
    for (int e = tid; e < 128 * 16; e += 256) {
        int i = e >> 4, d4 = e & 15;
        const float* base = qkv + (size_t)(chunk * PSZ + half * 128 + i) * C3;
        float4 qv = *(const float4*)(base + head * DHEAD + d4 * 4);
        uint32_t* dst = Qs + i * QS_STRIDE + d4 * 4;
        dst[0] = f2tf32(qv.x * 0.125f); dst[1] = f2tf32(qv.y * 0.125f);
        dst[2] = f2tf32(qv.z * 0.125f); dst[3] = f2tf32(qv.w * 0.125f);
    }
    if (half == 0 && tid < 64)
        cq[tid] = clsrow[head * DHEAD + tid] * 0.125f;
    __syncthreads();

    const int warp = tid >> 5, lane = tid & 31;
    const int g = lane >> 2, t = lane & 3;
    const int mrow = warp * 16;

    uint32_t qf[8][4];
    #pragma unroll
    for (int ks = 0; ks < 8; ks++) {
        qf[ks][0] = Qs[(mrow + g)     * QS_STRIDE + ks * 8 + t];
        qf[ks][1] = Qs[(mrow + g + 8) * QS_STRIDE + ks * 8 + t];
        qf[ks][2] = Qs[(mrow + g)     * QS_STRIDE + ks * 8 + t + 4];
        qf[ks][3] = Qs[(mrow + g + 8) * QS_STRIDE + ks * 8 + t + 4];
    }
    __syncwarp();

    float o[8][4];
    #pragma unroll
    for (int nt = 0; nt < 8; nt++)
        #pragma unroll
        for (int r = 0; r < 4; r++) o[nt][r] = 0.f;
    float m0 = -1e30f, m1 = -1e30f, l0 = 0.f, l1 = 0.f;

    for (int kb = 0; kb < 5; kb++) {
        const int nnt = (kb < 4) ? 8 : 1;
        float s[8][4];
        #pragma unroll
        for (int nt = 0; nt < 8; nt++)
            #pragma unroll
            for (int r = 0; r < 4; r++) s[nt][r] = 0.f;

        #pragma unroll
        for (int ks = 0; ks < 8; ks++) {
            #pragma unroll
            for (int nt = 0; nt < 8; nt++) {
                if (nt >= nnt) break;
                uint32_t b0 = Kt[(ks * 8 + t)     * KT_STRIDE + kb * 64 + nt * 8 + g];
                uint32_t b1 = Kt[(ks * 8 + t + 4) * KT_STRIDE + kb * 64 + nt * 8 + g];
                mma_tf32(s[nt], qf[ks], b0, b1);
            }
        }
        if (kb == 4) {
            if (t != 0) { s[0][0] = -1e30f; s[0][2] = -1e30f; }
            s[0][1] = -1e30f; s[0][3] = -1e30f;
        }

        float mx0 = -1e30f, mx1 = -1e30f;
        #pragma unroll
        for (int nt = 0; nt < 8; nt++) {
            if (nt >= nnt) break;
            mx0 = fmaxf(mx0, fmaxf(s[nt][0], s[nt][1]));
            mx1 = fmaxf(mx1, fmaxf(s[nt][2], s[nt][3]));
        }
        mx0 = fmaxf(mx0, __shfl_xor_sync(0xffffffffu, mx0, 1));
        mx0 = fmaxf(mx0, __shfl_xor_sync(0xffffffffu, mx0, 2));
        mx1 = fmaxf(mx1, __shfl_xor_sync(0xffffffffu, mx1, 1));
        mx1 = fmaxf(mx1, __shfl_xor_sync(0xffffffffu, mx1, 2));
        float nm0 = fmaxf(m0, mx0), nm1 = fmaxf(m1, mx1);
        float f0 = __expf(m0 - nm0), f1 = __expf(m1 - nm1);
        m0 = nm0; m1 = nm1; l0 *= f0; l1 *= f1;
        #pragma unroll
        for (int nt = 0; nt < 8; nt++) {
            o[nt][0] *= f0; o[nt][1] *= f0;
            o[nt][2] *= f1; o[nt][3] *= f1;
        }
        #pragma unroll
        for (int nt = 0; nt < 8; nt++) {
            if (nt >= nnt) break;
            float p0 = __expf(s[nt][0] - m0), p1 = __expf(s[nt][1] - m0);
            float p2 = __expf(s[nt][2] - m1), p3 = __expf(s[nt][3] - m1);
            l0 += p0 + p1; l1 += p2 + p3;
            Qs[(mrow + g)     * QS_STRIDE + nt * 8 + 2 * t]     = f2tf32(p0);
            Qs[(mrow + g)     * QS_STRIDE + nt * 8 + 2 * t + 1] = f2tf32(p1);
            Qs[(mrow + g + 8) * QS_STRIDE + nt * 8 + 2 * t]     = f2tf32(p2);
            Qs[(mrow + g + 8) * QS_STRIDE + nt * 8 + 2 * t + 1] = f2tf32(p3);
        }
        __syncwarp();

        const int nks = (kb < 4) ? 8 : 1;
        #pragma unroll
        for (int ks = 0; ks < 8; ks++) {
            if (ks >= nks) break;
            uint32_t pf[4];
            pf[0] = Qs[(mrow + g)     * QS_STRIDE + ks * 8 + t];
            pf[1] = Qs[(mrow + g + 8) * QS_STRIDE + ks * 8 + t];
            pf[2] = Qs[(mrow + g)     * QS_STRIDE + ks * 8 + t + 4];
            pf[3] = Qs[(mrow + g + 8) * QS_STRIDE + ks * 8 + t + 4];
            #pragma unroll
            for (int nt = 0; nt < 8; nt++) {
                uint32_t b0 = Vs[(kb * 64 + ks * 8 + t)     * VS_STRIDE + nt * 8 + g];
                uint32_t b1 = Vs[(kb * 64 + ks * 8 + t + 4) * VS_STRIDE + nt * 8 + g];
                mma_tf32(o[nt], pf, b0, b1);
            }
        }
        __syncwarp();
    }

    l0 += __shfl_xor_sync(0xffffffffu, l0, 1);
    l0 += __shfl_xor_sync(0xffffffffu, l0, 2);
    l1 += __shfl_xor_sync(0xffffffffu, l1, 1);
    l1 += __shfl_xor_sync(0xffffffffu, l1, 2);
    const float inv0 = 1.f / l0, inv1 = 1.f / l1;

    const int q0 = chunk * PSZ + half * 128 + mrow + g;
    const int dr0 = order[q0];
    const int dr1 = order[q0 + 8];
    #pragma unroll
    for (int nt = 0; nt < 8; nt++) {
        const int col = head * DHEAD + nt * 8 + 2 * t;
        float2 v0 = make_float2(o[nt][0] * inv0, o[nt][1] * inv0);
        float2 v1 = make_float2(o[nt][2] * inv1, o[nt][3] * inv1);
        *(float2*)(outp + (size_t)dr0 * CHN + col) = v0;
        *(float2*)(outp + (size_t)dr1 * CHN + col) = v1;
    }

    // ---- cls-query attention epilogue (half==0 blocks; K/V still in smem) --
    if (half == 0) {
        __syncthreads();
        // scores: thread j -> key j (column reads of Kt, conflict-free)
        for (int key = tid; key < 257; key += 256) {
            float s = 0.f;
            #pragma unroll
            for (int d = 0; d < 64; d++)
                s += cq[d] * __uint_as_float(Kt[d * KT_STRIDE + key]);
            cps[key] = s;
        }
        __syncthreads();
        if (tid < 32) {
            float mx = -1e30f;
            for (int j = tid; j < 257; j += 32) mx = fmaxf(mx, cps[j]);
            #pragma unroll
            for (int d = 16; d >= 1; d >>= 1)
                mx = fmaxf(mx, __shfl_xor_sync(0xffffffffu, mx, d));
            float sum = 0.f;
            for (int j = tid; j < 257; j += 32) {
                float p = __expf(cps[j] - mx);
                cps[j] = p;
                sum += p;
            }
            #pragma unroll
            for (int d = 16; d >= 1; d >>= 1)
                sum += __shfl_xor_sync(0xffffffffu, sum, d);
            if (tid == 0) cstat[1] = 1.f / sum;
        }
        __syncthreads();
        // PV: 4 threads per dim d, strided keys
        {
            const int d = tid & 63, q = tid >> 6;
            float a = 0.f;
            for (int j = q; j < 257; j += 4)
                a += cps[j] * __uint_as_float(Vs[j * VS_STRIDE + d]);
            cpart[tid] = a;
        }
        __syncthreads();
        if (tid < 64) {
            float a = cpart[tid] + cpart[64 + tid] + cpart[128 + tid] + cpart[192 + tid];
            cls_out[(size_t)chunk * CHN + head * DHEAD + tid] = a * cstat[1];
        }
    }
}

// ---------------- K5: cls_feat = per-batch mean of cls_out ------------
__global__ void cls_feat_kernel(const float* __restrict__ cls_out,
                                const int* __restrict__ offset,
                                float* __restrict__ out) {
    int b = blockIdx.x;
    int c = threadIdx.x;
    int o0 = offset[0], o1 = offset[1], o2 = offset[2], o3 = offset[3];
    float s = 0.f, cnt = 0.f;
    for (int ch = 0; ch < NCHUNK; ch++) {
        int start = ch * PSZ;
        int bid = (start >= o0) + (start >= o1) + (start >= o2) + (start >= o3);
        if (bid == b) { s += cls_out[(size_t)ch * CHN + c]; cnt += 1.f; }
    }
    out[(size_t)b * CHN + c] = s / cnt;
}

// ---------------- launch ----------------
extern "C" void kernel_launch(void* const* d_in, const int* in_sizes, int n_in,
                              void* d_out, int out_size) {
    const float* feat       = (const float*)d_in[0];
    const float* cls_tokens = (const float*)d_in[1];
    const float* Wqkv       = (const float*)d_in[2];
    const float* bqkv       = (const float*)d_in[3];
    const float* Wproj      = (const float*)d_in[4];
    const float* bproj      = (const float*)d_in[5];
    const int*   order      = (const int*)d_in[6];
    const int*   inverse    = (const int*)d_in[7];
    const int*   offset     = (const int*)d_in[8];
    float* out = (float*)d_out;

    float *qkv_p, *outp_p, *clsout_p, *clsqkv_p;
    cudaGetSymbolAddress((void**)&qkv_p, g_qkv);
    cudaGetSymbolAddress((void**)&outp_p, g_outp);
    cudaGetSymbolAddress((void**)&clsout_p, g_cls_out);
    cudaGetSymbolAddress((void**)&clsqkv_p, g_cls_qkv);

    cudaFuncSetAttribute(tgemm_kernel<0>, cudaFuncAttributeMaxDynamicSharedMemorySize, GEMM_SMEM);
    cudaFuncSetAttribute(tgemm_kernel<1>, cudaFuncAttributeMaxDynamicSharedMemorySize, GEMM_SMEM);
    cudaFuncSetAttribute(attn_tc_kernel, cudaFuncAttributeMaxDynamicSharedMemorySize, AT_SMEM);

    // K1: cls qkv (tiny)
    cls_qkv_kernel<<<(NBATCH * C3 + 255) / 256, 256>>>(cls_tokens, Wqkv, bqkv, clsqkv_p);

    // K2: qkv = feat @ Wqkv + bqkv, rows scattered by inverse -> serialized order
    tgemm_kernel<0><<<dim3(C3 / 128, NPTS / 128), 256, GEMM_SMEM>>>(
        feat, Wqkv, bqkv, qkv_p, inverse, CHN, CHN, C3, C3);

    // K3: tensor-core flash attention (point queries + fused cls queries)
    attn_tc_kernel<<<NCHUNK * NHEAD * 2, 256, AT_SMEM>>>(
        qkv_p, clsqkv_p, order, offset, outp_p, clsout_p);

    // K4: feat_out = outp @ Wproj + bproj
    tgemm_kernel<1><<<dim3(CHN / 128, NPTS / 128), 256, GEMM_SMEM>>>(
        outp_p, Wproj, bproj, out, nullptr, CHN, CHN, CHN, CHN);

    // K5: cls_feat
    cls_feat_kernel<<<NBATCH, CHN>>>(clsout_p, offset, out + (size_t)NPTS * CHN);
}

// round 8
// speedup vs baseline: 4.8890x; 1.2961x over previous
#include <cuda_runtime.h>
#include <cstdint>
#include <cstddef>

#define NPTS   65536
#define CHN    512
#define C3     1536
#define PSZ    256
#define NHEAD  8
#define DHEAD  64
#define NBATCH 4
#define NCHUNK (NPTS / PSZ)   // 256

// ---------------- scratch (device globals: allocation-free) ----------------
__device__ float g_qkv[(size_t)NPTS * C3];       // serialized-order qkv (tf32-rounded)
__device__ float g_outp[(size_t)NPTS * CHN];     // attention out (tf32-rounded)
__device__ float g_featc[(size_t)NPTS * CHN];    // tf32-rounded feat
__device__ float g_wqkvc[(size_t)CHN * C3];      // tf32-rounded Wqkv
__device__ float g_wprojc[(size_t)CHN * CHN];    // tf32-rounded Wproj
__device__ float g_cls_out[NCHUNK * CHN];
__device__ float g_cls_qkv[NBATCH * C3];

__device__ __forceinline__ uint32_t f2tf32(float f) {
    uint32_t u;
    asm("cvt.rna.tf32.f32 %0, %1;" : "=r"(u) : "f"(f));
    return u;
}
__device__ __forceinline__ float rnd_tf32(float f) {
    return __uint_as_float(f2tf32(f));
}

__device__ __forceinline__ void mma_tf32(float* c, const uint32_t* a,
                                         uint32_t b0, uint32_t b1) {
    asm volatile(
        "mma.sync.aligned.m16n8k8.row.col.f32.tf32.tf32.f32 "
        "{%0,%1,%2,%3}, {%4,%5,%6,%7}, {%8,%9}, {%0,%1,%2,%3};"
        : "+f"(c[0]), "+f"(c[1]), "+f"(c[2]), "+f"(c[3])
        : "r"(a[0]), "r"(a[1]), "r"(a[2]), "r"(a[3]), "r"(b0), "r"(b1));
}

__device__ __forceinline__ void cp16(uint32_t smem_addr, const void* gptr) {
    asm volatile("cp.async.cg.shared.global [%0], [%1], 16;"
                 :: "r"(smem_addr), "l"(gptr) : "memory");
}
__device__ __forceinline__ void cp_commit() {
    asm volatile("cp.async.commit_group;" ::: "memory");
}
template <int N>
__device__ __forceinline__ void cp_wait() {
    asm volatile("cp.async.wait_group %0;" :: "n"(N) : "memory");
}

// ---------------- K0: tf32 pre-rounding copy ----------------
__global__ void cvt_tf32_kernel(const float* __restrict__ in,
                                float* __restrict__ out, int n4) {
    int i = blockIdx.x * blockDim.x + threadIdx.x;
    if (i >= n4) return;
    float4 v = ((const float4*)in)[i];
    v.x = rnd_tf32(v.x); v.y = rnd_tf32(v.y);
    v.z = rnd_tf32(v.z); v.w = rnd_tf32(v.w);
    ((float4*)out)[i] = v;
}

// ---------------- K1: cls_qkv = cls_tokens @ Wqkv + bqkv (tf32-rounded out) -
__global__ void cls_qkv_kernel(const float* __restrict__ cls_tokens,
                               const float* __restrict__ Wqkv,
                               const float* __restrict__ bqkv,
                               float* __restrict__ cls_qkv) {
    int idx = blockIdx.x * blockDim.x + threadIdx.x;
    if (idx >= NBATCH * C3) return;
    int b = idx / C3, o = idx % C3;
    float s = bqkv[o];
    #pragma unroll 4
    for (int k = 0; k < CHN; k++)
        s += cls_tokens[b * CHN + k] * Wqkv[(size_t)k * C3 + o];
    cls_qkv[idx] = rnd_tf32(s);
}

// ------ tf32 GEMM: 128x128x32, 256 thr, cp.async 3-stage, 2 CTAs/SM -------
// Inputs A, B are PRE-ROUNDED tf32 values stored as float. No cvt in loop.
#define AS_STRIDE 36
#define BS_STRIDE 136
#define AS_BUF (128 * AS_STRIDE)
#define BS_BUF (32 * BS_STRIDE)
#define NSTAGE 3
#define GEMM_SMEM (NSTAGE * (AS_BUF + BS_BUF) * 4)   // 107520 bytes

template <int MODE>   // 0: scatter rows by rowmap + tf32-round output; 1: direct fp32
__global__ __launch_bounds__(256, 2)
void tgemm_kernel(const float* __restrict__ A, const float* __restrict__ B,
                  const float* __restrict__ bias, float* __restrict__ Cout,
                  const int* __restrict__ rowmap,
                  int Kdim, int lda, int ldb, int ldc) {
    extern __shared__ float smf[];
    uint32_t* As = (uint32_t*)smf;
    uint32_t* Bs = (uint32_t*)smf + NSTAGE * AS_BUF;

    const int tid  = threadIdx.x;
    const int lane = tid & 31;
    const int warp = tid >> 5;
    const int wm   = warp >> 2;
    const int wn   = warp & 3;
    const int g    = lane >> 2;
    const int t    = lane & 3;

    const int a_row = tid >> 1;
    const int a_k0  = (tid & 1) * 16;
    const float* Aptr = A + (size_t)(blockIdx.y * 128 + a_row) * lda + a_k0;
    const float* Bbase = B + blockIdx.x * 128;

    const uint32_t as_s = (uint32_t)__cvta_generic_to_shared(As + a_row * AS_STRIDE + a_k0);
    const int b_r  = tid >> 5;
    const int b_c4 = tid & 31;
    const uint32_t bs_s = (uint32_t)__cvta_generic_to_shared(Bs + b_r * BS_STRIDE + b_c4 * 4);

    auto issue = [&](int kt, int buf) {
        const float* ag = Aptr + kt * 32;
        uint32_t ad = as_s + buf * (AS_BUF * 4);
        cp16(ad,      ag);
        cp16(ad + 16, ag + 4);
        cp16(ad + 32, ag + 8);
        cp16(ad + 48, ag + 12);
        const float* bg = Bbase + (size_t)(kt * 32 + b_r) * ldb + b_c4 * 4;
        uint32_t bd = bs_s + buf * (BS_BUF * 4);
        #pragma unroll
        for (int i = 0; i < 4; i++)
            cp16(bd + i * (8 * BS_STRIDE * 4), bg + (size_t)(8 * i) * ldb);
    };

    const int nk = Kdim >> 5;
    issue(0, 0); cp_commit();
    issue(1, 1); cp_commit();

    float c[4][4][4];
    #pragma unroll
    for (int mi = 0; mi < 4; mi++)
        #pragma unroll
        for (int ni = 0; ni < 4; ni++)
            #pragma unroll
            for (int r = 0; r < 4; r++) c[mi][ni][r] = 0.f;

    for (int kt = 0; kt < nk; kt++) {
        const int cur = kt % NSTAGE;
        if (kt + 1 < nk) cp_wait<1>(); else cp_wait<0>();
        __syncthreads();
        if (kt + 2 < nk) { issue(kt + 2, (kt + 2) % NSTAGE); cp_commit(); }

        const uint32_t* asb = As + cur * AS_BUF;
        const uint32_t* bsb = Bs + cur * BS_BUF;
        #pragma unroll
        for (int ks = 0; ks < 4; ks++) {
            const int k0 = ks * 8;
            uint32_t af[4][4], bf[4][2];
            #pragma unroll
            for (int mi = 0; mi < 4; mi++) {
                const int row = wm * 64 + mi * 16 + g;
                af[mi][0] = asb[(row)     * AS_STRIDE + k0 + t];
                af[mi][1] = asb[(row + 8) * AS_STRIDE + k0 + t];
                af[mi][2] = asb[(row)     * AS_STRIDE + k0 + t + 4];
                af[mi][3] = asb[(row + 8) * AS_STRIDE + k0 + t + 4];
            }
            #pragma unroll
            for (int ni = 0; ni < 4; ni++) {
                const int col = wn * 32 + ni * 8 + g;
                bf[ni][0] = bsb[(k0 + t)     * BS_STRIDE + col];
                bf[ni][1] = bsb[(k0 + t + 4) * BS_STRIDE + col];
            }
            #pragma unroll
            for (int mi = 0; mi < 4; mi++)
                #pragma unroll
                for (int ni = 0; ni < 4; ni++)
                    mma_tf32(c[mi][ni], af[mi], bf[ni][0], bf[ni][1]);
        }
    }

    float2 bv[4];
    #pragma unroll
    for (int ni = 0; ni < 4; ni++)
        bv[ni] = *(const float2*)&bias[blockIdx.x * 128 + wn * 32 + ni * 8 + t * 2];

    #pragma unroll
    for (int mi = 0; mi < 4; mi++) {
        const int m0 = blockIdx.y * 128 + wm * 64 + mi * 16 + g;
        const int r0 = (MODE == 0) ? rowmap[m0]     : m0;
        const int r1 = (MODE == 0) ? rowmap[m0 + 8] : m0 + 8;
        #pragma unroll
        for (int ni = 0; ni < 4; ni++) {
            const int col = blockIdx.x * 128 + wn * 32 + ni * 8 + t * 2;
            float2 v0 = make_float2(c[mi][ni][0] + bv[ni].x, c[mi][ni][1] + bv[ni].y);
            float2 v1 = make_float2(c[mi][ni][2] + bv[ni].x, c[mi][ni][3] + bv[ni].y);
            if (MODE == 0) {
                v0.x = rnd_tf32(v0.x); v0.y = rnd_tf32(v0.y);
                v1.x = rnd_tf32(v1.x); v1.y = rnd_tf32(v1.y);
            }
            *(float2*)(Cout + (size_t)r0 * ldc + col) = v0;
            *(float2*)(Cout + (size_t)r1 * ldc + col) = v1;
        }
    }
}

// ---------------- K3: tensor-core flash attention ----------
// Block = 512 thr (16 warps), one block per (chunk, head); 256 queries/block.
// qkv and cls_qkv values are PRE-ROUNDED tf32 -> fills are raw copies.
// Keys 0..255 = chunk points, key 256 = cls token, 257..263 = zero pad.
#define KT_STRIDE 264
#define VS_STRIDE 72
#define QS_STRIDE 72
#define KT_WORDS (64 * KT_STRIDE)          // 16896
#define VS_WORDS (264 * VS_STRIDE)         // 19008
#define QS_WORDS (256 * QS_STRIDE)         // 18432
#define AT_SMEM ((KT_WORDS + VS_WORDS + QS_WORDS) * 4)   // 217344 bytes

__global__ __launch_bounds__(512)
void attn_tc_kernel(const float* __restrict__ qkv,
                    const float* __restrict__ cls_qkv,
                    const int* __restrict__ order,
                    const int* __restrict__ offset,
                    float* __restrict__ outp,
                    float* __restrict__ cls_out) {
    extern __shared__ uint32_t sm[];
    uint32_t* Kt = sm;
    uint32_t* Vs = sm + KT_WORDS;
    uint32_t* Qs = sm + KT_WORDS + VS_WORDS;

    __shared__ float cq[64];
    __shared__ float cps[257];
    __shared__ float cpart[512];
    __shared__ float cinv;

    const int chunk = blockIdx.x >> 3;
    const int head  = blockIdx.x & 7;
    const int tid   = threadIdx.x;

    const int start = chunk * PSZ;
    const int bid = (start >= offset[0]) + (start >= offset[1]) +
                    (start >= offset[2]) + (start >= offset[3]);
    const float* clsrow = cls_qkv + (size_t)bid * C3;

    // zero pad
    for (int e = tid; e < 64 * 7; e += 512) {
        int d = e / 7, k = e % 7;
        Kt[d * KT_STRIDE + 257 + k] = 0;
    }
    for (int e = tid; e < 7 * VS_STRIDE; e += 512)
        Vs[257 * VS_STRIDE + e] = 0;

    // K: one key per thread, transposed store (lane==key -> conflict-free)
    for (int key = tid; key < 257; key += 512) {
        const float* base = (key < 256)
            ? qkv + (size_t)(chunk * PSZ + key) * C3 : clsrow;
        #pragma unroll
        for (int d4 = 0; d4 < 16; d4++) {
            float4 kv = *(const float4*)(base + CHN + head * DHEAD + d4 * 4);
            Kt[(d4 * 4 + 0) * KT_STRIDE + key] = __float_as_uint(kv.x);
            Kt[(d4 * 4 + 1) * KT_STRIDE + key] = __float_as_uint(kv.y);
            Kt[(d4 * 4 + 2) * KT_STRIDE + key] = __float_as_uint(kv.z);
            Kt[(d4 * 4 + 3) * KT_STRIDE + key] = __float_as_uint(kv.w);
        }
    }
    // V
    for (int e = tid; e < 257 * 16; e += 512) {
        int key = e >> 4, d4 = e & 15;
        const float* base = (key < 256)
            ? qkv + (size_t)(chunk * PSZ + key) * C3 : clsrow;
        float4 vv = *(const float4*)(base + 2 * CHN + head * DHEAD + d4 * 4);
        uint32_t* dst = Vs + key * VS_STRIDE + d4 * 4;
        dst[0] = __float_as_uint(vv.x); dst[1] = __float_as_uint(vv.y);
        dst[2] = __float_as_uint(vv.z); dst[3] = __float_as_uint(vv.w);
    }
    // Q (x0.125: exact power of 2, stays tf32)
    for (int e = tid; e < 256 * 16; e += 512) {
        int i = e >> 4, d4 = e & 15;
        const float* base = qkv + (size_t)(chunk * PSZ + i) * C3;
        float4 qv = *(const float4*)(base + head * DHEAD + d4 * 4);
        uint32_t* dst = Qs + i * QS_STRIDE + d4 * 4;
        dst[0] = __float_as_uint(qv.x * 0.125f);
        dst[1] = __float_as_uint(qv.y * 0.125f);
        dst[2] = __float_as_uint(qv.z * 0.125f);
        dst[3] = __float_as_uint(qv.w * 0.125f);
    }
    if (tid < 64) cq[tid] = clsrow[head * DHEAD + tid] * 0.125f;
    __syncthreads();

    const int warp = tid >> 5, lane = tid & 31;
    const int g = lane >> 2, t = lane & 3;
    const int mrow = warp * 16;          // 0..240

    uint32_t qf[8][4];
    #pragma unroll
    for (int ks = 0; ks < 8; ks++) {
        qf[ks][0] = Qs[(mrow + g)     * QS_STRIDE + ks * 8 + t];
        qf[ks][1] = Qs[(mrow + g + 8) * QS_STRIDE + ks * 8 + t];
        qf[ks][2] = Qs[(mrow + g)     * QS_STRIDE + ks * 8 + t + 4];
        qf[ks][3] = Qs[(mrow + g + 8) * QS_STRIDE + ks * 8 + t + 4];
    }
    __syncwarp();

    float o[8][4];
    #pragma unroll
    for (int nt = 0; nt < 8; nt++)
        #pragma unroll
        for (int r = 0; r < 4; r++) o[nt][r] = 0.f;
    float m0 = -1e30f, m1 = -1e30f, l0 = 0.f, l1 = 0.f;

    for (int kb = 0; kb < 5; kb++) {
        const int nnt = (kb < 4) ? 8 : 1;
        float s[8][4];
        #pragma unroll
        for (int nt = 0; nt < 8; nt++)
            #pragma unroll
            for (int r = 0; r < 4; r++) s[nt][r] = 0.f;

        #pragma unroll
        for (int ks = 0; ks < 8; ks++) {
            #pragma unroll
            for (int nt = 0; nt < 8; nt++) {
                if (nt >= nnt) break;
                uint32_t b0 = Kt[(ks * 8 + t)     * KT_STRIDE + kb * 64 + nt * 8 + g];
                uint32_t b1 = Kt[(ks * 8 + t + 4) * KT_STRIDE + kb * 64 + nt * 8 + g];
                mma_tf32(s[nt], qf[ks], b0, b1);
            }
        }
        if (kb == 4) {
            if (t != 0) { s[0][0] = -1e30f; s[0][2] = -1e30f; }
            s[0][1] = -1e30f; s[0][3] = -1e30f;
        }

        float mx0 = -1e30f, mx1 = -1e30f;
        #pragma unroll
        for (int nt = 0; nt < 8; nt++) {
            if (nt >= nnt) break;
            mx0 = fmaxf(mx0, fmaxf(s[nt][0], s[nt][1]));
            mx1 = fmaxf(mx1, fmaxf(s[nt][2], s[nt][3]));
        }
        mx0 = fmaxf(mx0, __shfl_xor_sync(0xffffffffu, mx0, 1));
        mx0 = fmaxf(mx0, __shfl_xor_sync(0xffffffffu, mx0, 2));
        mx1 = fmaxf(mx1, __shfl_xor_sync(0xffffffffu, mx1, 1));
        mx1 = fmaxf(mx1, __shfl_xor_sync(0xffffffffu, mx1, 2));
        float nm0 = fmaxf(m0, mx0), nm1 = fmaxf(m1, mx1);
        float f0 = __expf(m0 - nm0), f1 = __expf(m1 - nm1);
        m0 = nm0; m1 = nm1; l0 *= f0; l1 *= f1;
        #pragma unroll
        for (int nt = 0; nt < 8; nt++) {
            o[nt][0] *= f0; o[nt][1] *= f0;
            o[nt][2] *= f1; o[nt][3] *= f1;
        }
        #pragma unroll
        for (int nt = 0; nt < 8; nt++) {
            if (nt >= nnt) break;
            float p0 = __expf(s[nt][0] - m0), p1 = __expf(s[nt][1] - m0);
            float p2 = __expf(s[nt][2] - m1), p3 = __expf(s[nt][3] - m1);
            l0 += p0 + p1; l1 += p2 + p3;
            Qs[(mrow + g)     * QS_STRIDE + nt * 8 + 2 * t]     = f2tf32(p0);
            Qs[(mrow + g)     * QS_STRIDE + nt * 8 + 2 * t + 1] = f2tf32(p1);
            Qs[(mrow + g + 8) * QS_STRIDE + nt * 8 + 2 * t]     = f2tf32(p2);
            Qs[(mrow + g + 8) * QS_STRIDE + nt * 8 + 2 * t + 1] = f2tf32(p3);
        }
        __syncwarp();

        const int nks = (kb < 4) ? 8 : 1;
        #pragma unroll
        for (int ks = 0; ks < 8; ks++) {
            if (ks >= nks) break;
            uint32_t pf[4];
            pf[0] = Qs[(mrow + g)     * QS_STRIDE + ks * 8 + t];
            pf[1] = Qs[(mrow + g + 8) * QS_STRIDE + ks * 8 + t];
            pf[2] = Qs[(mrow + g)     * QS_STRIDE + ks * 8 + t + 4];
            pf[3] = Qs[(mrow + g + 8) * QS_STRIDE + ks * 8 + t + 4];
            #pragma unroll
            for (int nt = 0; nt < 8; nt++) {
                uint32_t b0 = Vs[(kb * 64 + ks * 8 + t)     * VS_STRIDE + nt * 8 + g];
                uint32_t b1 = Vs[(kb * 64 + ks * 8 + t + 4) * VS_STRIDE + nt * 8 + g];
                mma_tf32(o[nt], pf, b0, b1);
            }
        }
        __syncwarp();
    }

    l0 += __shfl_xor_sync(0xffffffffu, l0, 1);
    l0 += __shfl_xor_sync(0xffffffffu, l0, 2);
    l1 += __shfl_xor_sync(0xffffffffu, l1, 1);
    l1 += __shfl_xor_sync(0xffffffffu, l1, 2);
    const float inv0 = 1.f / l0, inv1 = 1.f / l1;

    const int q0 = chunk * PSZ + mrow + g;
    const int dr0 = order[q0];
    const int dr1 = order[q0 + 8];
    #pragma unroll
    for (int nt = 0; nt < 8; nt++) {
        const int col = head * DHEAD + nt * 8 + 2 * t;
        // tf32-round here so proj GEMM consumes pre-rounded A (bit-identical
        // to previous fragment-time cvt)
        float2 v0 = make_float2(rnd_tf32(o[nt][0] * inv0), rnd_tf32(o[nt][1] * inv0));
        float2 v1 = make_float2(rnd_tf32(o[nt][2] * inv1), rnd_tf32(o[nt][3] * inv1));
        *(float2*)(outp + (size_t)dr0 * CHN + col) = v0;
        *(float2*)(outp + (size_t)dr1 * CHN + col) = v1;
    }

    // ---- cls-query attention epilogue (K/V still in smem) ----
    __syncthreads();
    for (int key = tid; key < 257; key += 512) {
        float s = 0.f;
        #pragma unroll
        for (int d = 0; d < 64; d++)
            s += cq[d] * __uint_as_float(Kt[d * KT_STRIDE + key]);
        cps[key] = s;
    }
    __syncthreads();
    if (tid < 32) {
        float mx = -1e30f;
        for (int j = tid; j < 257; j += 32) mx = fmaxf(mx, cps[j]);
        #pragma unroll
        for (int d = 16; d >= 1; d >>= 1)
            mx = fmaxf(mx, __shfl_xor_sync(0xffffffffu, mx, d));
        float sum = 0.f;
        for (int j = tid; j < 257; j += 32) {
            float p = __expf(cps[j] - mx);
            cps[j] = p;
            sum += p;
        }
        #pragma unroll
        for (int d = 16; d >= 1; d >>= 1)
            sum += __shfl_xor_sync(0xffffffffu, sum, d);
        if (tid == 0) cinv = 1.f / sum;
    }
    __syncthreads();
    {
        const int d = tid & 63, q = tid >> 6;     // 8 partials per dim
        float a = 0.f;
        for (int j = q; j < 257; j += 8)
            a += cps[j] * __uint_as_float(Vs[j * VS_STRIDE + d]);
        cpart[tid] = a;
    }
    __syncthreads();
    if (tid < 64) {
        float a = 0.f;
        #pragma unroll
        for (int q = 0; q < 8; q++) a += cpart[q * 64 + tid];
        cls_out[(size_t)chunk * CHN + head * DHEAD + tid] = a * cinv;
    }
}

// ---------------- K5: cls_feat = per-batch mean of cls_out ------------
__global__ void cls_feat_kernel(const float* __restrict__ cls_out,
                                const int* __restrict__ offset,
                                float* __restrict__ out) {
    int b = blockIdx.x;
    int c = threadIdx.x;
    int o0 = offset[0], o1 = offset[1], o2 = offset[2], o3 = offset[3];
    float s = 0.f, cnt = 0.f;
    for (int ch = 0; ch < NCHUNK; ch++) {
        int start = ch * PSZ;
        int bid = (start >= o0) + (start >= o1) + (start >= o2) + (start >= o3);
        if (bid == b) { s += cls_out[(size_t)ch * CHN + c]; cnt += 1.f; }
    }
    out[(size_t)b * CHN + c] = s / cnt;
}

// ---------------- launch ----------------
extern "C" void kernel_launch(void* const* d_in, const int* in_sizes, int n_in,
                              void* d_out, int out_size) {
    const float* feat       = (const float*)d_in[0];
    const float* cls_tokens = (const float*)d_in[1];
    const float* Wqkv       = (const float*)d_in[2];
    const float* bqkv       = (const float*)d_in[3];
    const float* Wproj      = (const float*)d_in[4];
    const float* bproj      = (const float*)d_in[5];
    const int*   order      = (const int*)d_in[6];
    const int*   inverse    = (const int*)d_in[7];
    const int*   offset     = (const int*)d_in[8];
    float* out = (float*)d_out;

    float *qkv_p, *outp_p, *clsout_p, *clsqkv_p, *featc_p, *wqkvc_p, *wprojc_p;
    cudaGetSymbolAddress((void**)&qkv_p, g_qkv);
    cudaGetSymbolAddress((void**)&outp_p, g_outp);
    cudaGetSymbolAddress((void**)&clsout_p, g_cls_out);
    cudaGetSymbolAddress((void**)&clsqkv_p, g_cls_qkv);
    cudaGetSymbolAddress((void**)&featc_p, g_featc);
    cudaGetSymbolAddress((void**)&wqkvc_p, g_wqkvc);
    cudaGetSymbolAddress((void**)&wprojc_p, g_wprojc);

    cudaFuncSetAttribute(tgemm_kernel<0>, cudaFuncAttributeMaxDynamicSharedMemorySize, GEMM_SMEM);
    cudaFuncSetAttribute(tgemm_kernel<1>, cudaFuncAttributeMaxDynamicSharedMemorySize, GEMM_SMEM);
    cudaFuncSetAttribute(attn_tc_kernel, cudaFuncAttributeMaxDynamicSharedMemorySize, AT_SMEM);

    // K0: tf32 pre-rounding copies
    {
        int n4 = NPTS * CHN / 4;
        cvt_tf32_kernel<<<(n4 + 255) / 256, 256>>>(feat, featc_p, n4);
        n4 = CHN * C3 / 4;
        cvt_tf32_kernel<<<(n4 + 255) / 256, 256>>>(Wqkv, wqkvc_p, n4);
        n4 = CHN * CHN / 4;
        cvt_tf32_kernel<<<(n4 + 255) / 256, 256>>>(Wproj, wprojc_p, n4);
    }

    // K1: cls qkv (tiny)
    cls_qkv_kernel<<<(NBATCH * C3 + 255) / 256, 256>>>(cls_tokens, Wqkv, bqkv, clsqkv_p);

    // K2: qkv = feat @ Wqkv + bqkv, scattered by inverse, tf32-rounded output
    tgemm_kernel<0><<<dim3(C3 / 128, NPTS / 128), 256, GEMM_SMEM>>>(
        featc_p, wqkvc_p, bqkv, qkv_p, inverse, CHN, CHN, C3, C3);

    // K3: flash attention (256 point queries + cls query per block)
    attn_tc_kernel<<<NCHUNK * NHEAD, 512, AT_SMEM>>>(
        qkv_p, clsqkv_p, order, offset, outp_p, clsout_p);

    // K4: feat_out = outp @ Wproj + bproj
    tgemm_kernel<1><<<dim3(CHN / 128, NPTS / 128), 256, GEMM_SMEM>>>(
        outp_p, wprojc_p, bproj, out, nullptr, CHN, CHN, CHN, CHN);

    // K5: cls_feat
    cls_feat_kernel<<<NBATCH, CHN>>>(clsout_p, offset, out + (size_t)NPTS * CHN);
}

// round 9
// speedup vs baseline: 5.0137x; 1.0255x over previous
#include <cuda_runtime.h>
#include <cstdint>
#include <cstddef>

#define NPTS   65536
#define CHN    512
#define C3     1536
#define PSZ    256
#define NHEAD  8
#define DHEAD  64
#define NBATCH 4
#define NCHUNK (NPTS / PSZ)   // 256

// log2(e) folded into the attention scale: softmax uses exp2
#define ATT_SCALE (0.125f * 1.44269504088896340736f)

// ---------------- scratch (device globals: allocation-free) ----------------
__device__ float g_qkv[(size_t)NPTS * C3];       // serialized-order qkv (tf32-rounded)
__device__ float g_outp[(size_t)NPTS * CHN];     // attention out (tf32-rounded)
__device__ float g_featc[(size_t)NPTS * CHN];    // tf32-rounded feat
__device__ float g_wqkvc[(size_t)CHN * C3];      // tf32-rounded Wqkv
__device__ float g_wprojc[(size_t)CHN * CHN];    // tf32-rounded Wproj
__device__ float g_cls_out[NCHUNK * CHN];
__device__ float g_cls_qkv[NBATCH * C3];

__device__ __forceinline__ uint32_t f2tf32(float f) {
    uint32_t u;
    asm("cvt.rna.tf32.f32 %0, %1;" : "=r"(u) : "f"(f));
    return u;
}
__device__ __forceinline__ float rnd_tf32(float f) {
    return __uint_as_float(f2tf32(f));
}

__device__ __forceinline__ void mma_tf32(float* c, const uint32_t* a,
                                         uint32_t b0, uint32_t b1) {
    asm volatile(
        "mma.sync.aligned.m16n8k8.row.col.f32.tf32.tf32.f32 "
        "{%0,%1,%2,%3}, {%4,%5,%6,%7}, {%8,%9}, {%0,%1,%2,%3};"
        : "+f"(c[0]), "+f"(c[1]), "+f"(c[2]), "+f"(c[3])
        : "r"(a[0]), "r"(a[1]), "r"(a[2]), "r"(a[3]), "r"(b0), "r"(b1));
}

__device__ __forceinline__ void cp16(uint32_t smem_addr, const void* gptr) {
    asm volatile("cp.async.cg.shared.global [%0], [%1], 16;"
                 :: "r"(smem_addr), "l"(gptr) : "memory");
}
__device__ __forceinline__ void cp_commit() {
    asm volatile("cp.async.commit_group;" ::: "memory");
}
template <int N>
__device__ __forceinline__ void cp_wait() {
    asm volatile("cp.async.wait_group %0;" :: "n"(N) : "memory");
}

// ---------------- K0: tf32 pre-rounding copy ----------------
__global__ void cvt_tf32_kernel(const float* __restrict__ in,
                                float* __restrict__ out, int n4) {
    int i = blockIdx.x * blockDim.x + threadIdx.x;
    if (i >= n4) return;
    float4 v = ((const float4*)in)[i];
    v.x = rnd_tf32(v.x); v.y = rnd_tf32(v.y);
    v.z = rnd_tf32(v.z); v.w = rnd_tf32(v.w);
    ((float4*)out)[i] = v;
}

// ---------------- K1: cls_qkv = cls_tokens @ Wqkv + bqkv ----------------
// Warp per output element, lanes split K 32-way (was serial-K, 64us latency-bound)
__global__ __launch_bounds__(256)
void cls_qkv_kernel(const float* __restrict__ cls_tokens,
                    const float* __restrict__ Wqkv,
                    const float* __restrict__ bqkv,
                    float* __restrict__ cls_qkv) {
    const int w = blockIdx.x * 8 + (threadIdx.x >> 5);   // 0..6143
    const int lane = threadIdx.x & 31;
    const int b = w / C3, o = w - b * C3;
    float s = 0.f;
    #pragma unroll
    for (int k = lane; k < CHN; k += 32)
        s += cls_tokens[b * CHN + k] * Wqkv[(size_t)k * C3 + o];
    #pragma unroll
    for (int d = 16; d >= 1; d >>= 1)
        s += __shfl_xor_sync(0xffffffffu, s, d);
    if (lane == 0) cls_qkv[w] = rnd_tf32(s + bqkv[o]);
}

// ------ tf32 GEMM: 128x128x32, 256 thr, cp.async 3-stage, 2 CTAs/SM -------
// Inputs A, B are PRE-ROUNDED tf32 values stored as float. No cvt in loop.
#define AS_STRIDE 36
#define BS_STRIDE 136
#define AS_BUF (128 * AS_STRIDE)
#define BS_BUF (32 * BS_STRIDE)
#define NSTAGE 3
#define GEMM_SMEM (NSTAGE * (AS_BUF + BS_BUF) * 4)   // 107520 bytes

template <int MODE>   // 0: scatter rows by rowmap + tf32-round output; 1: direct fp32
__global__ __launch_bounds__(256, 2)
void tgemm_kernel(const float* __restrict__ A, const float* __restrict__ B,
                  const float* __restrict__ bias, float* __restrict__ Cout,
                  const int* __restrict__ rowmap,
                  int Kdim, int lda, int ldb, int ldc) {
    extern __shared__ float smf[];
    uint32_t* As = (uint32_t*)smf;
    uint32_t* Bs = (uint32_t*)smf + NSTAGE * AS_BUF;

    const int tid  = threadIdx.x;
    const int lane = tid & 31;
    const int warp = tid >> 5;
    const int wm   = warp >> 2;
    const int wn   = warp & 3;
    const int g    = lane >> 2;
    const int t    = lane & 3;

    const int a_row = tid >> 1;
    const int a_k0  = (tid & 1) * 16;
    const float* Aptr = A + (size_t)(blockIdx.y * 128 + a_row) * lda + a_k0;
    const float* Bbase = B + blockIdx.x * 128;

    const uint32_t as_s = (uint32_t)__cvta_generic_to_shared(As + a_row * AS_STRIDE + a_k0);
    const int b_r  = tid >> 5;
    const int b_c4 = tid & 31;
    const uint32_t bs_s = (uint32_t)__cvta_generic_to_shared(Bs + b_r * BS_STRIDE + b_c4 * 4);

    auto issue = [&](int kt, int buf) {
        const float* ag = Aptr + kt * 32;
        uint32_t ad = as_s + buf * (AS_BUF * 4);
        cp16(ad,      ag);
        cp16(ad + 16, ag + 4);
        cp16(ad + 32, ag + 8);
        cp16(ad + 48, ag + 12);
        const float* bg = Bbase + (size_t)(kt * 32 + b_r) * ldb + b_c4 * 4;
        uint32_t bd = bs_s + buf * (BS_BUF * 4);
        #pragma unroll
        for (int i = 0; i < 4; i++)
            cp16(bd + i * (8 * BS_STRIDE * 4), bg + (size_t)(8 * i) * ldb);
    };

    const int nk = Kdim >> 5;
    issue(0, 0); cp_commit();
    issue(1, 1); cp_commit();

    float c[4][4][4];
    #pragma unroll
    for (int mi = 0; mi < 4; mi++)
        #pragma unroll
        for (int ni = 0; ni < 4; ni++)
            #pragma unroll
            for (int r = 0; r < 4; r++) c[mi][ni][r] = 0.f;

    for (int kt = 0; kt < nk; kt++) {
        const int cur = kt % NSTAGE;
        if (kt + 1 < nk) cp_wait<1>(); else cp_wait<0>();
        __syncthreads();
        if (kt + 2 < nk) { issue(kt + 2, (kt + 2) % NSTAGE); cp_commit(); }

        const uint32_t* asb = As + cur * AS_BUF;
        const uint32_t* bsb = Bs + cur * BS_BUF;
        #pragma unroll
        for (int ks = 0; ks < 4; ks++) {
            const int k0 = ks * 8;
            uint32_t af[4][4], bf[4][2];
            #pragma unroll
            for (int mi = 0; mi < 4; mi++) {
                const int row = wm * 64 + mi * 16 + g;
                af[mi][0] = asb[(row)     * AS_STRIDE + k0 + t];
                af[mi][1] = asb[(row + 8) * AS_STRIDE + k0 + t];
                af[mi][2] = asb[(row)     * AS_STRIDE + k0 + t + 4];
                af[mi][3] = asb[(row + 8) * AS_STRIDE + k0 + t + 4];
            }
            #pragma unroll
            for (int ni = 0; ni < 4; ni++) {
                const int col = wn * 32 + ni * 8 + g;
                bf[ni][0] = bsb[(k0 + t)     * BS_STRIDE + col];
                bf[ni][1] = bsb[(k0 + t + 4) * BS_STRIDE + col];
            }
            #pragma unroll
            for (int mi = 0; mi < 4; mi++)
                #pragma unroll
                for (int ni = 0; ni < 4; ni++)
                    mma_tf32(c[mi][ni], af[mi], bf[ni][0], bf[ni][1]);
        }
    }

    float2 bv[4];
    #pragma unroll
    for (int ni = 0; ni < 4; ni++)
        bv[ni] = *(const float2*)&bias[blockIdx.x * 128 + wn * 32 + ni * 8 + t * 2];

    #pragma unroll
    for (int mi = 0; mi < 4; mi++) {
        const int m0 = blockIdx.y * 128 + wm * 64 + mi * 16 + g;
        const int r0 = (MODE == 0) ? rowmap[m0]     : m0;
        const int r1 = (MODE == 0) ? rowmap[m0 + 8] : m0 + 8;
        #pragma unroll
        for (int ni = 0; ni < 4; ni++) {
            const int col = blockIdx.x * 128 + wn * 32 + ni * 8 + t * 2;
            float2 v0 = make_float2(c[mi][ni][0] + bv[ni].x, c[mi][ni][1] + bv[ni].y);
            float2 v1 = make_float2(c[mi][ni][2] + bv[ni].x, c[mi][ni][3] + bv[ni].y);
            if (MODE == 0) {
                v0.x = rnd_tf32(v0.x); v0.y = rnd_tf32(v0.y);
                v1.x = rnd_tf32(v1.x); v1.y = rnd_tf32(v1.y);
            }
            *(float2*)(Cout + (size_t)r0 * ldc + col) = v0;
            *(float2*)(Cout + (size_t)r1 * ldc + col) = v1;
        }
    }
}

// ---------------- K3: tensor-core flash attention ----------
// Block = 512 thr (16 warps), one block per (chunk, head); 256 queries/block.
// Q pre-scaled by 0.125*log2e -> softmax via exp2 (no FMUL per exp).
#define KT_STRIDE 264
#define VS_STRIDE 72
#define QS_STRIDE 72
#define KT_WORDS (64 * KT_STRIDE)          // 16896
#define VS_WORDS (264 * VS_STRIDE)         // 19008
#define QS_WORDS (256 * QS_STRIDE)         // 18432
#define AT_SMEM ((KT_WORDS + VS_WORDS + QS_WORDS) * 4)   // 217344 bytes

__global__ __launch_bounds__(512)
void attn_tc_kernel(const float* __restrict__ qkv,
                    const float* __restrict__ cls_qkv,
                    const int* __restrict__ order,
                    const int* __restrict__ offset,
                    float* __restrict__ outp,
                    float* __restrict__ cls_out) {
    extern __shared__ uint32_t sm[];
    uint32_t* Kt = sm;
    uint32_t* Vs = sm + KT_WORDS;
    uint32_t* Qs = sm + KT_WORDS + VS_WORDS;

    __shared__ float cq[64];
    __shared__ float cps[257];
    __shared__ float cpart[512];
    __shared__ float cinv;

    const int chunk = blockIdx.x >> 3;
    const int head  = blockIdx.x & 7;
    const int tid   = threadIdx.x;

    const int start = chunk * PSZ;
    const int bid = (start >= offset[0]) + (start >= offset[1]) +
                    (start >= offset[2]) + (start >= offset[3]);
    const float* clsrow = cls_qkv + (size_t)bid * C3;

    // zero pad
    for (int e = tid; e < 64 * 7; e += 512) {
        int d = e / 7, k = e % 7;
        Kt[d * KT_STRIDE + 257 + k] = 0;
    }
    for (int e = tid; e < 7 * VS_STRIDE; e += 512)
        Vs[257 * VS_STRIDE + e] = 0;

    // K: one key per thread, transposed store
    for (int key = tid; key < 257; key += 512) {
        const float* base = (key < 256)
            ? qkv + (size_t)(chunk * PSZ + key) * C3 : clsrow;
        #pragma unroll
        for (int d4 = 0; d4 < 16; d4++) {
            float4 kv = *(const float4*)(base + CHN + head * DHEAD + d4 * 4);
            Kt[(d4 * 4 + 0) * KT_STRIDE + key] = __float_as_uint(kv.x);
            Kt[(d4 * 4 + 1) * KT_STRIDE + key] = __float_as_uint(kv.y);
            Kt[(d4 * 4 + 2) * KT_STRIDE + key] = __float_as_uint(kv.z);
            Kt[(d4 * 4 + 3) * KT_STRIDE + key] = __float_as_uint(kv.w);
        }
    }
    // V
    for (int e = tid; e < 257 * 16; e += 512) {
        int key = e >> 4, d4 = e & 15;
        const float* base = (key < 256)
            ? qkv + (size_t)(chunk * PSZ + key) * C3 : clsrow;
        float4 vv = *(const float4*)(base + 2 * CHN + head * DHEAD + d4 * 4);
        uint32_t* dst = Vs + key * VS_STRIDE + d4 * 4;
        dst[0] = __float_as_uint(vv.x); dst[1] = __float_as_uint(vv.y);
        dst[2] = __float_as_uint(vv.z); dst[3] = __float_as_uint(vv.w);
    }
    // Q: fold 0.125*log2e, re-round to tf32 (scale not a power of 2)
    for (int e = tid; e < 256 * 16; e += 512) {
        int i = e >> 4, d4 = e & 15;
        const float* base = qkv + (size_t)(chunk * PSZ + i) * C3;
        float4 qv = *(const float4*)(base + head * DHEAD + d4 * 4);
        uint32_t* dst = Qs + i * QS_STRIDE + d4 * 4;
        dst[0] = f2tf32(qv.x * ATT_SCALE);
        dst[1] = f2tf32(qv.y * ATT_SCALE);
        dst[2] = f2tf32(qv.z * ATT_SCALE);
        dst[3] = f2tf32(qv.w * ATT_SCALE);
    }
    if (tid < 64) cq[tid] = clsrow[head * DHEAD + tid] * ATT_SCALE;
    __syncthreads();

    const int warp = tid >> 5, lane = tid & 31;
    const int g = lane >> 2, t = lane & 3;
    const int mrow = warp * 16;

    uint32_t qf[8][4];
    #pragma unroll
    for (int ks = 0; ks < 8; ks++) {
        qf[ks][0] = Qs[(mrow + g)     * QS_STRIDE + ks * 8 + t];
        qf[ks][1] = Qs[(mrow + g + 8) * QS_STRIDE + ks * 8 + t];
        qf[ks][2] = Qs[(mrow + g)     * QS_STRIDE + ks * 8 + t + 4];
        qf[ks][3] = Qs[(mrow + g + 8) * QS_STRIDE + ks * 8 + t + 4];
    }
    __syncwarp();

    float o[8][4];
    #pragma unroll
    for (int nt = 0; nt < 8; nt++)
        #pragma unroll
        for (int r = 0; r < 4; r++) o[nt][r] = 0.f;
    float m0 = -1e30f, m1 = -1e30f, l0 = 0.f, l1 = 0.f;

    for (int kb = 0; kb < 5; kb++) {
        const int nnt = (kb < 4) ? 8 : 1;
        float s[8][4];
        #pragma unroll
        for (int nt = 0; nt < 8; nt++)
            #pragma unroll
            for (int r = 0; r < 4; r++) s[nt][r] = 0.f;

        #pragma unroll
        for (int ks = 0; ks < 8; ks++) {
            #pragma unroll
            for (int nt = 0; nt < 8; nt++) {
                if (nt >= nnt) break;
                uint32_t b0 = Kt[(ks * 8 + t)     * KT_STRIDE + kb * 64 + nt * 8 + g];
                uint32_t b1 = Kt[(ks * 8 + t + 4) * KT_STRIDE + kb * 64 + nt * 8 + g];
                mma_tf32(s[nt], qf[ks], b0, b1);
            }
        }
        if (kb == 4) {
            if (t != 0) { s[0][0] = -1e30f; s[0][2] = -1e30f; }
            s[0][1] = -1e30f; s[0][3] = -1e30f;
        }

        float mx0 = -1e30f, mx1 = -1e30f;
        #pragma unroll
        for (int nt = 0; nt < 8; nt++) {
            if (nt >= nnt) break;
            mx0 = fmaxf(mx0, fmaxf(s[nt][0], s[nt][1]));
            mx1 = fmaxf(mx1, fmaxf(s[nt][2], s[nt][3]));
        }
        mx0 = fmaxf(mx0, __shfl_xor_sync(0xffffffffu, mx0, 1));
        mx0 = fmaxf(mx0, __shfl_xor_sync(0xffffffffu, mx0, 2));
        mx1 = fmaxf(mx1, __shfl_xor_sync(0xffffffffu, mx1, 1));
        mx1 = fmaxf(mx1, __shfl_xor_sync(0xffffffffu, mx1, 2));
        float nm0 = fmaxf(m0, mx0), nm1 = fmaxf(m1, mx1);
        float f0 = exp2f(m0 - nm0), f1 = exp2f(m1 - nm1);
        m0 = nm0; m1 = nm1; l0 *= f0; l1 *= f1;
        #pragma unroll
        for (int nt = 0; nt < 8; nt++) {
            o[nt][0] *= f0; o[nt][1] *= f0;
            o[nt][2] *= f1; o[nt][3] *= f1;
        }
        #pragma unroll
        for (int nt = 0; nt < 8; nt++) {
            if (nt >= nnt) break;
            float p0 = exp2f(s[nt][0] - m0), p1 = exp2f(s[nt][1] - m0);
            float p2 = exp2f(s[nt][2] - m1), p3 = exp2f(s[nt][3] - m1);
            l0 += p0 + p1; l1 += p2 + p3;
            Qs[(mrow + g)     * QS_STRIDE + nt * 8 + 2 * t]     = f2tf32(p0);
            Qs[(mrow + g)     * QS_STRIDE + nt * 8 + 2 * t + 1] = f2tf32(p1);
            Qs[(mrow + g + 8) * QS_STRIDE + nt * 8 + 2 * t]     = f2tf32(p2);
            Qs[(mrow + g + 8) * QS_STRIDE + nt * 8 + 2 * t + 1] = f2tf32(p3);
        }
        __syncwarp();

        const int nks = (kb < 4) ? 8 : 1;
        #pragma unroll
        for (int ks = 0; ks < 8; ks++) {
            if (ks >= nks) break;
            uint32_t pf[4];
            pf[0] = Qs[(mrow + g)     * QS_STRIDE + ks * 8 + t];
            pf[1] = Qs[(mrow + g + 8) * QS_STRIDE + ks * 8 + t];
            pf[2] = Qs[(mrow + g)     * QS_STRIDE + ks * 8 + t + 4];
            pf[3] = Qs[(mrow + g + 8) * QS_STRIDE + ks * 8 + t + 4];
            #pragma unroll
            for (int nt = 0; nt < 8; nt++) {
                uint32_t b0 = Vs[(kb * 64 + ks * 8 + t)     * VS_STRIDE + nt * 8 + g];
                uint32_t b1 = Vs[(kb * 64 + ks * 8 + t + 4) * VS_STRIDE + nt * 8 + g];
                mma_tf32(o[nt], pf, b0, b1);
            }
        }
        __syncwarp();
    }

    l0 += __shfl_xor_sync(0xffffffffu, l0, 1);
    l0 += __shfl_xor_sync(0xffffffffu, l0, 2);
    l1 += __shfl_xor_sync(0xffffffffu, l1, 1);
    l1 += __shfl_xor_sync(0xffffffffu, l1, 2);
    const float inv0 = 1.f / l0, inv1 = 1.f / l1;

    const int q0 = chunk * PSZ + mrow + g;
    const int dr0 = order[q0];
    const int dr1 = order[q0 + 8];
    #pragma unroll
    for (int nt = 0; nt < 8; nt++) {
        const int col = head * DHEAD + nt * 8 + 2 * t;
        float2 v0 = make_float2(rnd_tf32(o[nt][0] * inv0), rnd_tf32(o[nt][1] * inv0));
        float2 v1 = make_float2(rnd_tf32(o[nt][2] * inv1), rnd_tf32(o[nt][3] * inv1));
        *(float2*)(outp + (size_t)dr0 * CHN + col) = v0;
        *(float2*)(outp + (size_t)dr1 * CHN + col) = v1;
    }

    // ---- cls-query attention epilogue (K/V still in smem) ----
    __syncthreads();
    for (int key = tid; key < 257; key += 512) {
        float s = 0.f;
        #pragma unroll
        for (int d = 0; d < 64; d++)
            s += cq[d] * __uint_as_float(Kt[d * KT_STRIDE + key]);
        cps[key] = s;
    }
    __syncthreads();
    if (tid < 32) {
        float mx = -1e30f;
        for (int j = tid; j < 257; j += 32) mx = fmaxf(mx, cps[j]);
        #pragma unroll
        for (int d = 16; d >= 1; d >>= 1)
            mx = fmaxf(mx, __shfl_xor_sync(0xffffffffu, mx, d));
        float sum = 0.f;
        for (int j = tid; j < 257; j += 32) {
            float p = exp2f(cps[j] - mx);
            cps[j] = p;
            sum += p;
        }
        #pragma unroll
        for (int d = 16; d >= 1; d >>= 1)
            sum += __shfl_xor_sync(0xffffffffu, sum, d);
        if (tid == 0) cinv = 1.f / sum;
    }
    __syncthreads();
    {
        const int d = tid & 63, q = tid >> 6;
        float a = 0.f;
        for (int j = q; j < 257; j += 8)
            a += cps[j] * __uint_as_float(Vs[j * VS_STRIDE + d]);
        cpart[tid] = a;
    }
    __syncthreads();
    if (tid < 64) {
        float a = 0.f;
        #pragma unroll
        for (int q = 0; q < 8; q++) a += cpart[q * 64 + tid];
        cls_out[(size_t)chunk * CHN + head * DHEAD + tid] = a * cinv;
    }
}

// ---------------- K5: cls_feat = per-batch mean of cls_out ------------
__global__ void cls_feat_kernel(const float* __restrict__ cls_out,
                                const int* __restrict__ offset,
                                float* __restrict__ out) {
    int b = blockIdx.x;
    int c = threadIdx.x;
    int o0 = offset[0], o1 = offset[1], o2 = offset[2], o3 = offset[3];
    float s = 0.f, cnt = 0.f;
    for (int ch = 0; ch < NCHUNK; ch++) {
        int start = ch * PSZ;
        int bid = (start >= o0) + (start >= o1) + (start >= o2) + (start >= o3);
        if (bid == b) { s += cls_out[(size_t)ch * CHN + c]; cnt += 1.f; }
    }
    out[(size_t)b * CHN + c] = s / cnt;
}

// ---------------- launch ----------------
extern "C" void kernel_launch(void* const* d_in, const int* in_sizes, int n_in,
                              void* d_out, int out_size) {
    const float* feat       = (const float*)d_in[0];
    const float* cls_tokens = (const float*)d_in[1];
    const float* Wqkv       = (const float*)d_in[2];
    const float* bqkv       = (const float*)d_in[3];
    const float* Wproj      = (const float*)d_in[4];
    const float* bproj      = (const float*)d_in[5];
    const int*   order      = (const int*)d_in[6];
    const int*   inverse    = (const int*)d_in[7];
    const int*   offset     = (const int*)d_in[8];
    float* out = (float*)d_out;

    float *qkv_p, *outp_p, *clsout_p, *clsqkv_p, *featc_p, *wqkvc_p, *wprojc_p;
    cudaGetSymbolAddress((void**)&qkv_p, g_qkv);
    cudaGetSymbolAddress((void**)&outp_p, g_outp);
    cudaGetSymbolAddress((void**)&clsout_p, g_cls_out);
    cudaGetSymbolAddress((void**)&clsqkv_p, g_cls_qkv);
    cudaGetSymbolAddress((void**)&featc_p, g_featc);
    cudaGetSymbolAddress((void**)&wqkvc_p, g_wqkvc);
    cudaGetSymbolAddress((void**)&wprojc_p, g_wprojc);

    cudaFuncSetAttribute(tgemm_kernel<0>, cudaFuncAttributeMaxDynamicSharedMemorySize, GEMM_SMEM);
    cudaFuncSetAttribute(tgemm_kernel<1>, cudaFuncAttributeMaxDynamicSharedMemorySize, GEMM_SMEM);
    cudaFuncSetAttribute(attn_tc_kernel, cudaFuncAttributeMaxDynamicSharedMemorySize, AT_SMEM);

    // K0: tf32 pre-rounding copies
    {
        int n4 = NPTS * CHN / 4;
        cvt_tf32_kernel<<<(n4 + 255) / 256, 256>>>(feat, featc_p, n4);
        n4 = CHN * C3 / 4;
        cvt_tf32_kernel<<<(n4 + 255) / 256, 256>>>(Wqkv, wqkvc_p, n4);
        n4 = CHN * CHN / 4;
        cvt_tf32_kernel<<<(n4 + 255) / 256, 256>>>(Wproj, wprojc_p, n4);
    }

    // K1: cls qkv (warp-per-output)
    cls_qkv_kernel<<<NBATCH * C3 / 8, 256>>>(cls_tokens, Wqkv, bqkv, clsqkv_p);

    // K2: qkv = feat @ Wqkv + bqkv, scattered by inverse, tf32-rounded output
    tgemm_kernel<0><<<dim3(C3 / 128, NPTS / 128), 256, GEMM_SMEM>>>(
        featc_p, wqkvc_p, bqkv, qkv_p, inverse, CHN, CHN, C3, C3);

    // K3: flash attention (256 point queries + cls query per block)
    attn_tc_kernel<<<NCHUNK * NHEAD, 512, AT_SMEM>>>(
        qkv_p, clsqkv_p, order, offset, outp_p, clsout_p);

    // K4: feat_out = outp @ Wproj + bproj
    tgemm_kernel<1><<<dim3(CHN / 128, NPTS / 128), 256, GEMM_SMEM>>>(
        outp_p, wprojc_p, bproj, out, nullptr, CHN, CHN, CHN, CHN);

    // K5: cls_feat
    cls_feat_kernel<<<NBATCH, CHN>>>(clsout_p, offset, out + (size_t)NPTS * CHN);
}